// round 10
// baseline (speedup 1.0000x reference)
#include <cuda_runtime.h>
#include <math.h>
#include <stdint.h>

// Problem constants
#define BATCH 2
#define NSEQ  2048
#define DMODEL 2048
#define NH    32
#define NKVH  8
#define HD    64
#define ROWS  4096       // BATCH * NSEQ
#define NQT   (NSEQ / 64)   // 32 q-tiles

// ---------------------------------------------------------------------------
// Scratch (device globals -- no allocation allowed anywhere)
// ---------------------------------------------------------------------------
__device__ float g_Q[(size_t)ROWS * DMODEL];
__device__ float g_K[(size_t)ROWS * (NKVH * HD)];
__device__ float g_V[(size_t)ROWS * (NKVH * HD)];
__device__ float g_O[(size_t)ROWS * DMODEL];
__device__ float g_xr[(size_t)ROWS * DMODEL];
__device__ float g_Wqr[(size_t)DMODEL * DMODEL];
__device__ float g_Wkr[(size_t)DMODEL * (NKVH * HD)];
__device__ float g_Wvr[(size_t)DMODEL * (NKVH * HD)];
__device__ float g_Wor[(size_t)DMODEL * DMODEL];

// ---------------------------------------------------------------------------
// Helpers
// ---------------------------------------------------------------------------
__device__ __forceinline__ void cp_async16(void* smem, const void* gmem) {
    uint32_t s = (uint32_t)__cvta_generic_to_shared(smem);
    asm volatile("cp.async.cg.shared.global [%0], [%1], 16;\n" ::"r"(s), "l"(gmem));
}
#define CP_COMMIT() asm volatile("cp.async.commit_group;\n" ::: "memory")
#define CP_WAIT0()  asm volatile("cp.async.wait_group 0;\n" ::: "memory")
#define CP_WAIT1()  asm volatile("cp.async.wait_group 1;\n" ::: "memory")

__device__ __forceinline__ uint32_t f2tf32(float x) {
    uint32_t r;
    asm("cvt.rna.tf32.f32 %0, %1;" : "=r"(r) : "f"(x));
    return r;
}
__device__ __forceinline__ float roundtf(float x) {
    return __uint_as_float(f2tf32(x));
}

__device__ __forceinline__ void mma_tf32(float* c, const uint32_t* a, const uint32_t* b) {
    asm volatile(
        "mma.sync.aligned.m16n8k8.row.col.f32.tf32.tf32.f32 "
        "{%0,%1,%2,%3}, {%4,%5,%6,%7}, {%8,%9}, {%0,%1,%2,%3};"
        : "+f"(c[0]), "+f"(c[1]), "+f"(c[2]), "+f"(c[3])
        : "r"(a[0]), "r"(a[1]), "r"(a[2]), "r"(a[3]), "r"(b[0]), "r"(b[1]));
}

// ---------------------------------------------------------------------------
// Fused tf32 rounding of x and all weights (one launch).
// ---------------------------------------------------------------------------
#define N4_X   ((ROWS * DMODEL) / 4)
#define N4_WQ  ((DMODEL * DMODEL) / 4)
#define N4_WKV ((DMODEL * NKVH * HD) / 4)
#define N4_ALL (N4_X + N4_WQ + 2 * N4_WKV + N4_WQ)

__global__ void round_all(const float4* __restrict__ x,
                          const float4* __restrict__ Wq,
                          const float4* __restrict__ Wk,
                          const float4* __restrict__ Wv,
                          const float4* __restrict__ Wo,
                          float4* __restrict__ xr,
                          float4* __restrict__ Wqr,
                          float4* __restrict__ Wkr,
                          float4* __restrict__ Wvr,
                          float4* __restrict__ Wor)
{
    int i = blockIdx.x * blockDim.x + threadIdx.x;
    if (i >= N4_ALL) return;
    const float4* src;
    float4* dst;
    int j = i;
    if (j < N4_X) { src = x; dst = xr; }
    else {
        j -= N4_X;
        if (j < N4_WQ) { src = Wq; dst = Wqr; }
        else {
            j -= N4_WQ;
            if (j < N4_WKV) { src = Wk; dst = Wkr; }
            else {
                j -= N4_WKV;
                if (j < N4_WKV) { src = Wv; dst = Wvr; }
                else { j -= N4_WKV; src = Wo; dst = Wor; }
            }
        }
    }
    float4 v = src[j];
    dst[j] = make_float4(roundtf(v.x), roundtf(v.y), roundtf(v.z), roundtf(v.w));
}

// ---------------------------------------------------------------------------
// GEMM tiling: block tile 128x128, BK=32, 3-stage cp.async pipeline.
// 512 threads = 16 warps in a 4x4 grid; warp tile 32x32 (acc 32 regs) so
// 2 CTAs/SM = 32 warps/SM (latency hiding). Regs capped at 64 by bounds.
// ---------------------------------------------------------------------------
#define APAD 36
#define BPAD 136
#define A_ST (128 * APAD)                 // 4608 floats
#define B_ST (32 * BPAD)                  // 4352 floats
#define GST  (A_ST + B_ST)                // 8960 floats per stage
#define GEMM_DYN (3 * GST * 4)            // 107520 bytes

// Fused QKV projection + RoPE epilogue.
// grid (24, 32): bx<16 -> Q tile; [16,20) -> K; [20,24) -> V.
__global__ __launch_bounds__(512, 2) void qkv_gemm(
    const float* __restrict__ A,
    const float* __restrict__ Wq, const float* __restrict__ Wk,
    const float* __restrict__ Wv,
    float* __restrict__ Qo, float* __restrict__ Ko, float* __restrict__ Vo,
    const float* __restrict__ fc, const float* __restrict__ fs)
{
    extern __shared__ float smf[];

    const int tid  = threadIdx.x;
    const int lane = tid & 31;
    const int wid  = tid >> 5;          // 0..15
    const int wm   = wid & 3;           // 4 warps along M
    const int wn   = wid >> 2;          // 4 warps along N
    const int gid  = lane >> 2;
    const int tig  = lane & 3;
    const int bx   = blockIdx.x;

    const float* B;
    float* C;
    int nTile, Ntot, doRope;
    if (bx < 16)      { B = Wq; C = Qo; nTile = bx;      Ntot = DMODEL;    doRope = 1; }
    else if (bx < 20) { B = Wk; C = Ko; nTile = bx - 16; Ntot = NKVH * HD; doRope = 1; }
    else              { B = Wv; C = Vo; nTile = bx - 20; Ntot = NKVH * HD; doRope = 0; }

    const int K = DMODEL;
    const float* Ab = A + (size_t)(blockIdx.y * 128) * K;
    const float* Bb = B + nTile * 128;

    // 512 threads: A stage 1024 float4 chunks (2/thread), B stage 1024 (2/thread)
    auto load_stage = [&](int kt, int s) {
        float* Ad = smf + s * GST;
        float* Bd = smf + s * GST + A_ST;
        const int k0 = kt * 32;
#pragma unroll
        for (int i = 0; i < 2; i++) {
            int c = tid + i * 512;
            int ar = c >> 3, akq = (c & 7) << 2;
            cp_async16(Ad + ar * APAD + akq, Ab + (size_t)ar * K + k0 + akq);
            int br = c >> 5, bnq = (c & 31) << 2;
            cp_async16(Bd + br * BPAD + bnq, Bb + (size_t)(k0 + br) * Ntot + bnq);
        }
    };

    float acc[2][4][4];
#pragma unroll
    for (int mt = 0; mt < 2; mt++)
#pragma unroll
        for (int nt = 0; nt < 4; nt++)
#pragma unroll
            for (int i = 0; i < 4; i++) acc[mt][nt][i] = 0.f;

    const int nk = K / 32;   // 64
    load_stage(0, 0); CP_COMMIT();
    load_stage(1, 1); CP_COMMIT();

    int st = 0;
    for (int kt = 0; kt < nk; kt++) {
        if (kt < nk - 1) { CP_WAIT1(); } else { CP_WAIT0(); }
        __syncthreads();

        if (kt + 2 < nk) {
            int s2 = st + 2; if (s2 >= 3) s2 -= 3;
            load_stage(kt + 2, s2);
            CP_COMMIT();
        }

        const float* Asb = smf + st * GST;
        const float* Bsb = smf + st * GST + A_ST;
#pragma unroll
        for (int ks = 0; ks < 4; ks++) {
            const int k0 = ks * 8;
            uint32_t a[2][4];
#pragma unroll
            for (int mt = 0; mt < 2; mt++) {
                const int mr = wm * 32 + mt * 16;
                a[mt][0] = __float_as_uint(Asb[(mr + gid) * APAD + k0 + tig]);
                a[mt][1] = __float_as_uint(Asb[(mr + gid + 8) * APAD + k0 + tig]);
                a[mt][2] = __float_as_uint(Asb[(mr + gid) * APAD + k0 + tig + 4]);
                a[mt][3] = __float_as_uint(Asb[(mr + gid + 8) * APAD + k0 + tig + 4]);
            }
            uint32_t b[4][2];
#pragma unroll
            for (int nt = 0; nt < 4; nt++) {
                const int nc = wn * 32 + nt * 8 + gid;
                b[nt][0] = __float_as_uint(Bsb[(k0 + tig) * BPAD + nc]);
                b[nt][1] = __float_as_uint(Bsb[(k0 + tig + 4) * BPAD + nc]);
            }
#pragma unroll
            for (int mt = 0; mt < 2; mt++)
#pragma unroll
                for (int nt = 0; nt < 4; nt++)
                    mma_tf32(acc[mt][nt], a[mt], b[nt]);
        }
        st++; if (st == 3) st = 0;
    }

    // Epilogue with fused RoPE (pairs are (even,odd) columns = acc[..][0/1]).
    const int cm = blockIdx.y * 128 + wm * 32;
    const int cn = nTile * 128 + wn * 32;
#pragma unroll
    for (int mt = 0; mt < 2; mt++) {
        const int r0 = cm + mt * 16 + gid;
        const int r1 = r0 + 8;
#pragma unroll
        for (int nt = 0; nt < 4; nt++) {
            const int col = cn + nt * 8 + 2 * tig;
            float* p0 = C + (size_t)r0 * Ntot + col;
            float* p1 = C + (size_t)r1 * Ntot + col;
            if (doRope) {
                const int p  = (col >> 1) & 31;
                const int n0 = r0 & (NSEQ - 1);
                const int n1 = r1 & (NSEQ - 1);
                float c0 = fc[n0 * 32 + p], s0 = fs[n0 * 32 + p];
                float c1 = fc[n1 * 32 + p], s1 = fs[n1 * 32 + p];
                float xr0 = acc[mt][nt][0], xi0 = acc[mt][nt][1];
                float xr1 = acc[mt][nt][2], xi1 = acc[mt][nt][3];
                *(float2*)p0 = make_float2(roundtf(xr0 * c0 - xi0 * s0),
                                           roundtf(xr0 * s0 + xi0 * c0));
                *(float2*)p1 = make_float2(roundtf(xr1 * c1 - xi1 * s1),
                                           roundtf(xr1 * s1 + xi1 * c1));
            } else {
                *(float2*)p0 = make_float2(roundtf(acc[mt][nt][0]),
                                           roundtf(acc[mt][nt][1]));
                *(float2*)p1 = make_float2(roundtf(acc[mt][nt][2]),
                                           roundtf(acc[mt][nt][3]));
            }
        }
    }
}

// Plain GEMM for the output projection (same 512-thread structure).
__global__ __launch_bounds__(512, 2) void tf32gemm(
    const float* __restrict__ A, const float* __restrict__ B,
    float* __restrict__ C, int M, int N, int K)
{
    extern __shared__ float smf[];

    const int tid  = threadIdx.x;
    const int lane = tid & 31;
    const int wid  = tid >> 5;
    const int wm   = wid & 3;
    const int wn   = wid >> 2;
    const int gid  = lane >> 2;
    const int tig  = lane & 3;

    const float* Ab = A + (size_t)(blockIdx.y * 128) * K;
    const float* Bb = B + blockIdx.x * 128;

    auto load_stage = [&](int kt, int s) {
        float* Ad = smf + s * GST;
        float* Bd = smf + s * GST + A_ST;
        const int k0 = kt * 32;
#pragma unroll
        for (int i = 0; i < 2; i++) {
            int c = tid + i * 512;
            int ar = c >> 3, akq = (c & 7) << 2;
            cp_async16(Ad + ar * APAD + akq, Ab + (size_t)ar * K + k0 + akq);
            int br = c >> 5, bnq = (c & 31) << 2;
            cp_async16(Bd + br * BPAD + bnq, Bb + (size_t)(k0 + br) * N + bnq);
        }
    };

    float acc[2][4][4];
#pragma unroll
    for (int mt = 0; mt < 2; mt++)
#pragma unroll
        for (int nt = 0; nt < 4; nt++)
#pragma unroll
            for (int i = 0; i < 4; i++) acc[mt][nt][i] = 0.f;

    const int nk = K / 32;
    load_stage(0, 0); CP_COMMIT();
    load_stage(1, 1); CP_COMMIT();

    int st = 0;
    for (int kt = 0; kt < nk; kt++) {
        if (kt < nk - 1) { CP_WAIT1(); } else { CP_WAIT0(); }
        __syncthreads();

        if (kt + 2 < nk) {
            int s2 = st + 2; if (s2 >= 3) s2 -= 3;
            load_stage(kt + 2, s2);
            CP_COMMIT();
        }

        const float* Asb = smf + st * GST;
        const float* Bsb = smf + st * GST + A_ST;
#pragma unroll
        for (int ks = 0; ks < 4; ks++) {
            const int k0 = ks * 8;
            uint32_t a[2][4];
#pragma unroll
            for (int mt = 0; mt < 2; mt++) {
                const int mr = wm * 32 + mt * 16;
                a[mt][0] = __float_as_uint(Asb[(mr + gid) * APAD + k0 + tig]);
                a[mt][1] = __float_as_uint(Asb[(mr + gid + 8) * APAD + k0 + tig]);
                a[mt][2] = __float_as_uint(Asb[(mr + gid) * APAD + k0 + tig + 4]);
                a[mt][3] = __float_as_uint(Asb[(mr + gid + 8) * APAD + k0 + tig + 4]);
            }
            uint32_t b[4][2];
#pragma unroll
            for (int nt = 0; nt < 4; nt++) {
                const int nc = wn * 32 + nt * 8 + gid;
                b[nt][0] = __float_as_uint(Bsb[(k0 + tig) * BPAD + nc]);
                b[nt][1] = __float_as_uint(Bsb[(k0 + tig + 4) * BPAD + nc]);
            }
#pragma unroll
            for (int mt = 0; mt < 2; mt++)
#pragma unroll
                for (int nt = 0; nt < 4; nt++)
                    mma_tf32(acc[mt][nt], a[mt], b[nt]);
        }
        st++; if (st == 3) st = 0;
    }

    const int cm = blockIdx.y * 128 + wm * 32;
    const int cn = blockIdx.x * 128 + wn * 32;
#pragma unroll
    for (int mt = 0; mt < 2; mt++) {
#pragma unroll
        for (int nt = 0; nt < 4; nt++) {
            float* p0 = C + (size_t)(cm + mt * 16 + gid) * N + cn + nt * 8 + 2 * tig;
            float* p1 = p0 + (size_t)8 * N;
            *(float2*)p0 = make_float2(acc[mt][nt][0], acc[mt][nt][1]);
            *(float2*)p1 = make_float2(acc[mt][nt][2], acc[mt][nt][3]);
        }
    }
}

// ---------------------------------------------------------------------------
// Tensor-core flash attention (tf32), causal, GQA. LPT schedule.
// ---------------------------------------------------------------------------
#define KPITCH 68
#define VPITCH 72
#define PPITCH 68
#define KBUF (64 * KPITCH)
#define VBUF (64 * VPITCH)
#define SMEM_ATTN ((2 * KBUF + 2 * VBUF + 4 * 16 * PPITCH) * 4)

__global__ __launch_bounds__(128) void attn_tc(
    const float* __restrict__ Q, const float* __restrict__ Kg,
    const float* __restrict__ Vg, float* __restrict__ O)
{
    extern __shared__ char smem_raw[];
    float*    sK = (float*)smem_raw;
    float*    sV = (float*)(smem_raw + 2 * KBUF * 4);
    uint32_t* sP = (uint32_t*)(smem_raw + (2 * KBUF + 2 * VBUF) * 4);

    const int qt = NQT - 1 - blockIdx.x;   // LPT: big tiles first
    const int h = blockIdx.y, b = blockIdx.z;
    const int kvh = h >> 2;
    const int tid = threadIdx.x;
    const int w = tid >> 5;
    const int lane = tid & 31;
    const int gid = lane >> 2, tig = lane & 3;

    const int qr0 = qt * 64 + w * 16 + gid;
    const int qr1 = qr0 + 8;

    uint32_t aq[8][4];
    {
        const float* q0 = Q + ((size_t)(b * NSEQ) + qr0) * DMODEL + h * HD;
        const float* q1 = Q + ((size_t)(b * NSEQ) + qr1) * DMODEL + h * HD;
#pragma unroll
        for (int ks = 0; ks < 8; ks++) {
            int d = ks * 8 + tig;
            aq[ks][0] = __float_as_uint(q0[d] * 0.125f);
            aq[ks][1] = __float_as_uint(q1[d] * 0.125f);
            aq[ks][2] = __float_as_uint(q0[d + 4] * 0.125f);
            aq[ks][3] = __float_as_uint(q1[d + 4] * 0.125f);
        }
    }

    float o[8][4];
#pragma unroll
    for (int nt = 0; nt < 8; nt++)
#pragma unroll
        for (int i = 0; i < 4; i++) o[nt][i] = 0.f;
    float m0 = -1e30f, l0 = 0.f, m1 = -1e30f, l1 = 0.f;

    const size_t kvs = NKVH * HD;

    auto load_tile = [&](int t, int st) {
        const float* kb = Kg + (size_t)(b * NSEQ + t * 64) * kvs + kvh * HD;
        const float* vb = Vg + (size_t)(b * NSEQ + t * 64) * kvs + kvh * HD;
        float* dK = sK + st * KBUF;
        float* dV = sV + st * VBUF;
#pragma unroll
        for (int i = 0; i < 8; i++) {
            int c = tid + i * 128;
            int r = c >> 4, c4 = (c & 15) << 2;
            cp_async16(dK + r * KPITCH + c4, kb + (size_t)r * kvs + c4);
            cp_async16(dV + r * VPITCH + c4, vb + (size_t)r * kvs + c4);
        }
    };

    load_tile(0, 0);
    CP_COMMIT();

    for (int t = 0; t <= qt; t++) {
        const int st = t & 1;
        CP_WAIT0();
        __syncthreads();

        if (t < qt) { load_tile(t + 1, st ^ 1); CP_COMMIT(); }

        const float* bK = sK + st * KBUF;
        const float* bV = sV + st * VBUF;

        float s[8][4];
#pragma unroll
        for (int nt = 0; nt < 8; nt++)
#pragma unroll
            for (int i = 0; i < 4; i++) s[nt][i] = 0.f;
#pragma unroll
        for (int ks = 0; ks < 8; ks++) {
            const int d0 = ks * 8;
#pragma unroll
            for (int nt = 0; nt < 8; nt++) {
                const float* kr = bK + (nt * 8 + gid) * KPITCH + d0 + tig;
                uint32_t bb[2];
                bb[0] = __float_as_uint(kr[0]);
                bb[1] = __float_as_uint(kr[4]);
                mma_tf32(s[nt], aq[ks], bb);
            }
        }

        if (t == qt) {
#pragma unroll
            for (int nt = 0; nt < 8; nt++) {
                int k0 = nt * 8 + 2 * tig;
                int r0 = w * 16 + gid;
                if (k0 > r0)         s[nt][0] = -1e30f;
                if (k0 + 1 > r0)     s[nt][1] = -1e30f;
                if (k0 > r0 + 8)     s[nt][2] = -1e30f;
                if (k0 + 1 > r0 + 8) s[nt][3] = -1e30f;
            }
        }

        float mx0 = -1e30f, mx1 = -1e30f;
#pragma unroll
        for (int nt = 0; nt < 8; nt++) {
            mx0 = fmaxf(mx0, fmaxf(s[nt][0], s[nt][1]));
            mx1 = fmaxf(mx1, fmaxf(s[nt][2], s[nt][3]));
        }
        mx0 = fmaxf(mx0, __shfl_xor_sync(0xffffffffu, mx0, 1));
        mx0 = fmaxf(mx0, __shfl_xor_sync(0xffffffffu, mx0, 2));
        mx1 = fmaxf(mx1, __shfl_xor_sync(0xffffffffu, mx1, 1));
        mx1 = fmaxf(mx1, __shfl_xor_sync(0xffffffffu, mx1, 2));

        float mn0 = fmaxf(m0, mx0), mn1 = fmaxf(m1, mx1);
        float c0 = __expf(m0 - mn0), c1 = __expf(m1 - mn1);
        float ls0 = 0.f, ls1 = 0.f;
#pragma unroll
        for (int nt = 0; nt < 8; nt++) {
            s[nt][0] = __expf(s[nt][0] - mn0);
            s[nt][1] = __expf(s[nt][1] - mn0);
            s[nt][2] = __expf(s[nt][2] - mn1);
            s[nt][3] = __expf(s[nt][3] - mn1);
            ls0 += s[nt][0] + s[nt][1];
            ls1 += s[nt][2] + s[nt][3];
        }
        ls0 += __shfl_xor_sync(0xffffffffu, ls0, 1);
        ls0 += __shfl_xor_sync(0xffffffffu, ls0, 2);
        ls1 += __shfl_xor_sync(0xffffffffu, ls1, 1);
        ls1 += __shfl_xor_sync(0xffffffffu, ls1, 2);
        l0 = l0 * c0 + ls0;
        l1 = l1 * c1 + ls1;
        m0 = mn0; m1 = mn1;
#pragma unroll
        for (int nt = 0; nt < 8; nt++) {
            o[nt][0] *= c0; o[nt][1] *= c0;
            o[nt][2] *= c1; o[nt][3] *= c1;
        }

        uint32_t* pw = sP + w * (16 * PPITCH);
#pragma unroll
        for (int nt = 0; nt < 8; nt++) {
            uint2 v0 = make_uint2(f2tf32(s[nt][0]), f2tf32(s[nt][1]));
            uint2 v1 = make_uint2(f2tf32(s[nt][2]), f2tf32(s[nt][3]));
            *(uint2*)(pw + gid * PPITCH + nt * 8 + 2 * tig) = v0;
            *(uint2*)(pw + (gid + 8) * PPITCH + nt * 8 + 2 * tig) = v1;
        }
        __syncwarp();

#pragma unroll
        for (int ks = 0; ks < 8; ks++) {
            const int k0 = ks * 8;
            uint32_t ap[4];
            ap[0] = pw[gid * PPITCH + k0 + tig];
            ap[1] = pw[(gid + 8) * PPITCH + k0 + tig];
            ap[2] = pw[gid * PPITCH + k0 + tig + 4];
            ap[3] = pw[(gid + 8) * PPITCH + k0 + tig + 4];
#pragma unroll
            for (int nt = 0; nt < 8; nt++) {
                const float* vr = bV + (k0 + tig) * VPITCH + nt * 8 + gid;
                uint32_t bb[2];
                bb[0] = __float_as_uint(vr[0]);
                bb[1] = __float_as_uint(vr[4 * VPITCH]);
                mma_tf32(o[nt], ap, bb);
            }
        }
    }

    float inv0 = 1.f / l0, inv1 = 1.f / l1;
    float* o0 = O + ((size_t)(b * NSEQ) + qr0) * DMODEL + h * HD;
    float* o1 = O + ((size_t)(b * NSEQ) + qr1) * DMODEL + h * HD;
#pragma unroll
    for (int nt = 0; nt < 8; nt++) {
        *(float2*)(o0 + nt * 8 + 2 * tig) =
            make_float2(roundtf(o[nt][0] * inv0), roundtf(o[nt][1] * inv0));
        *(float2*)(o1 + nt * 8 + 2 * tig) =
            make_float2(roundtf(o[nt][2] * inv1), roundtf(o[nt][3] * inv1));
    }
}

// ---------------------------------------------------------------------------
// Launch. Order: round_all(1), qkv(2), attn(3), O-gemm(4 = ncu slot).
// ---------------------------------------------------------------------------
extern "C" void kernel_launch(void* const* d_in, const int* in_sizes, int n_in,
                              void* d_out, int out_size)
{
    const float* x  = (const float*)d_in[0];
    const float* Wq = (const float*)d_in[1];
    const float* Wk = (const float*)d_in[2];
    const float* Wv = (const float*)d_in[3];
    const float* Wo = (const float*)d_in[4];
    const float* fc = (const float*)d_in[5];
    const float* fs = (const float*)d_in[6];
    float* out = (float*)d_out;

    float *Qp, *Kp, *Vp, *Op, *xr, *Wqr, *Wkr, *Wvr, *Wor;
    cudaGetSymbolAddress((void**)&Qp,  g_Q);
    cudaGetSymbolAddress((void**)&Kp,  g_K);
    cudaGetSymbolAddress((void**)&Vp,  g_V);
    cudaGetSymbolAddress((void**)&Op,  g_O);
    cudaGetSymbolAddress((void**)&xr,  g_xr);
    cudaGetSymbolAddress((void**)&Wqr, g_Wqr);
    cudaGetSymbolAddress((void**)&Wkr, g_Wkr);
    cudaGetSymbolAddress((void**)&Wvr, g_Wvr);
    cudaGetSymbolAddress((void**)&Wor, g_Wor);

    static bool attr_set = false;
    if (!attr_set) {
        cudaFuncSetAttribute(attn_tc,
            cudaFuncAttributeMaxDynamicSharedMemorySize, SMEM_ATTN);
        cudaFuncSetAttribute(qkv_gemm,
            cudaFuncAttributeMaxDynamicSharedMemorySize, GEMM_DYN);
        cudaFuncSetAttribute(tf32gemm,
            cudaFuncAttributeMaxDynamicSharedMemorySize, GEMM_DYN);
        attr_set = true;
    }

    // 1: fused tf32 rounding
    round_all<<<(N4_ALL + 255) / 256, 256>>>(
        (const float4*)x, (const float4*)Wq, (const float4*)Wk,
        (const float4*)Wv, (const float4*)Wo,
        (float4*)xr, (float4*)Wqr, (float4*)Wkr, (float4*)Wvr, (float4*)Wor);

    // 2: fused Q/K/V projection + RoPE (512-thread CTAs)
    qkv_gemm<<<dim3(24, ROWS / 128), 512, GEMM_DYN>>>(
        xr, Wqr, Wkr, Wvr, Qp, Kp, Vp, fc, fs);

    // 3: attention (LPT-ordered)
    attn_tc<<<dim3(NQT, NH, BATCH), 128, SMEM_ATTN>>>(Qp, Kp, Vp, Op);

    // 4: output projection  <-- ncu capture slot (512-thread CTAs)
    tf32gemm<<<dim3(DMODEL / 128, ROWS / 128), 512, GEMM_DYN>>>(
        Op, Wor, out, ROWS, DMODEL, DMODEL);
}

// round 13
// speedup vs baseline: 1.0605x; 1.0605x over previous
#include <cuda_runtime.h>
#include <math.h>
#include <stdint.h>

// Problem constants
#define BATCH 2
#define NSEQ  2048
#define DMODEL 2048
#define NH    32
#define NKVH  8
#define HD    64
#define ROWS  4096       // BATCH * NSEQ
#define NQT   (NSEQ / 64)   // 32 q-tiles

// ---------------------------------------------------------------------------
// Scratch (device globals -- no allocation allowed anywhere)
// ---------------------------------------------------------------------------
__device__ float g_Q[(size_t)ROWS * DMODEL];
__device__ float g_K[(size_t)ROWS * (NKVH * HD)];
__device__ float g_V[(size_t)ROWS * (NKVH * HD)];
__device__ float g_O[(size_t)ROWS * DMODEL];
__device__ float g_xr[(size_t)ROWS * DMODEL];
__device__ float g_Wqr[(size_t)DMODEL * DMODEL];
__device__ float g_Wkr[(size_t)DMODEL * (NKVH * HD)];
__device__ float g_Wvr[(size_t)DMODEL * (NKVH * HD)];
__device__ float g_Wor[(size_t)DMODEL * DMODEL];

// ---------------------------------------------------------------------------
// Helpers
// ---------------------------------------------------------------------------
__device__ __forceinline__ void cp_async16(void* smem, const void* gmem) {
    uint32_t s = (uint32_t)__cvta_generic_to_shared(smem);
    asm volatile("cp.async.cg.shared.global [%0], [%1], 16;\n" ::"r"(s), "l"(gmem));
}
#define CP_COMMIT() asm volatile("cp.async.commit_group;\n" ::: "memory")
#define CP_WAIT0()  asm volatile("cp.async.wait_group 0;\n" ::: "memory")
#define CP_WAIT1()  asm volatile("cp.async.wait_group 1;\n" ::: "memory")

__device__ __forceinline__ uint32_t f2tf32(float x) {
    uint32_t r;
    asm("cvt.rna.tf32.f32 %0, %1;" : "=r"(r) : "f"(x));
    return r;
}
__device__ __forceinline__ float roundtf(float x) {
    return __uint_as_float(f2tf32(x));
}

__device__ __forceinline__ void mma_tf32(float* c, const uint32_t* a, const uint32_t* b) {
    asm volatile(
        "mma.sync.aligned.m16n8k8.row.col.f32.tf32.tf32.f32 "
        "{%0,%1,%2,%3}, {%4,%5,%6,%7}, {%8,%9}, {%0,%1,%2,%3};"
        : "+f"(c[0]), "+f"(c[1]), "+f"(c[2]), "+f"(c[3])
        : "r"(a[0]), "r"(a[1]), "r"(a[2]), "r"(a[3]), "r"(b[0]), "r"(b[1]));
}

// ---------------------------------------------------------------------------
// Fused tf32 rounding of x and all weights (one launch).
// ---------------------------------------------------------------------------
#define N4_X   ((ROWS * DMODEL) / 4)
#define N4_WQ  ((DMODEL * DMODEL) / 4)
#define N4_WKV ((DMODEL * NKVH * HD) / 4)
#define N4_ALL (N4_X + N4_WQ + 2 * N4_WKV + N4_WQ)

__global__ void round_all(const float4* __restrict__ x,
                          const float4* __restrict__ Wq,
                          const float4* __restrict__ Wk,
                          const float4* __restrict__ Wv,
                          const float4* __restrict__ Wo,
                          float4* __restrict__ xr,
                          float4* __restrict__ Wqr,
                          float4* __restrict__ Wkr,
                          float4* __restrict__ Wvr,
                          float4* __restrict__ Wor)
{
    int i = blockIdx.x * blockDim.x + threadIdx.x;
    if (i >= N4_ALL) return;
    const float4* src;
    float4* dst;
    int j = i;
    if (j < N4_X) { src = x; dst = xr; }
    else {
        j -= N4_X;
        if (j < N4_WQ) { src = Wq; dst = Wqr; }
        else {
            j -= N4_WQ;
            if (j < N4_WKV) { src = Wk; dst = Wkr; }
            else {
                j -= N4_WKV;
                if (j < N4_WKV) { src = Wv; dst = Wvr; }
                else { j -= N4_WKV; src = Wo; dst = Wor; }
            }
        }
    }
    float4 v = src[j];
    dst[j] = make_float4(roundtf(v.x), roundtf(v.y), roundtf(v.z), roundtf(v.w));
}

// ---------------------------------------------------------------------------
// GEMM tiling (R9 config -- measured best): block 128x128, BK=32, 3-stage
// cp.async, 256 threads (8 warps, 4m x 2n, warp tile 32x64).
// ---------------------------------------------------------------------------
#define APAD 36
#define BPAD 136
#define A_ST (128 * APAD)                 // 4608 floats
#define B_ST (32 * BPAD)                  // 4352 floats
#define GST  (A_ST + B_ST)                // 8960 floats per stage
#define GEMM_DYN (3 * GST * 4)            // 107520 bytes

// Fused QKV projection + RoPE epilogue.
// grid (24, 32): bx<16 -> Q tile; [16,20) -> K; [20,24) -> V.
__global__ __launch_bounds__(256, 2) void qkv_gemm(
    const float* __restrict__ A,
    const float* __restrict__ Wq, const float* __restrict__ Wk,
    const float* __restrict__ Wv,
    float* __restrict__ Qo, float* __restrict__ Ko, float* __restrict__ Vo,
    const float* __restrict__ fc, const float* __restrict__ fs)
{
    extern __shared__ float smf[];

    const int tid  = threadIdx.x;
    const int lane = tid & 31;
    const int wid  = tid >> 5;
    const int wm   = wid & 3;
    const int wn   = wid >> 2;
    const int gid  = lane >> 2;
    const int tig  = lane & 3;
    const int bx   = blockIdx.x;

    const float* B;
    float* C;
    int nTile, Ntot, doRope;
    if (bx < 16)      { B = Wq; C = Qo; nTile = bx;      Ntot = DMODEL;    doRope = 1; }
    else if (bx < 20) { B = Wk; C = Ko; nTile = bx - 16; Ntot = NKVH * HD; doRope = 1; }
    else              { B = Wv; C = Vo; nTile = bx - 20; Ntot = NKVH * HD; doRope = 0; }

    const int K = DMODEL;
    const float* Ab = A + (size_t)(blockIdx.y * 128) * K;
    const float* Bb = B + nTile * 128;

    auto load_stage = [&](int kt, int s) {
        float* Ad = smf + s * GST;
        float* Bd = smf + s * GST + A_ST;
        const int k0 = kt * 32;
#pragma unroll
        for (int i = 0; i < 4; i++) {
            int c = tid + i * 256;
            int ar = c >> 3, akq = (c & 7) << 2;
            cp_async16(Ad + ar * APAD + akq, Ab + (size_t)ar * K + k0 + akq);
            int br = c >> 5, bnq = (c & 31) << 2;
            cp_async16(Bd + br * BPAD + bnq, Bb + (size_t)(k0 + br) * Ntot + bnq);
        }
    };

    float acc[2][8][4];
#pragma unroll
    for (int mt = 0; mt < 2; mt++)
#pragma unroll
        for (int nt = 0; nt < 8; nt++)
#pragma unroll
            for (int i = 0; i < 4; i++) acc[mt][nt][i] = 0.f;

    const int nk = K / 32;   // 64
    load_stage(0, 0); CP_COMMIT();
    load_stage(1, 1); CP_COMMIT();

    int st = 0;
    for (int kt = 0; kt < nk; kt++) {
        if (kt < nk - 1) { CP_WAIT1(); } else { CP_WAIT0(); }
        __syncthreads();

        if (kt + 2 < nk) {
            int s2 = st + 2; if (s2 >= 3) s2 -= 3;
            load_stage(kt + 2, s2);
            CP_COMMIT();
        }

        const float* Asb = smf + st * GST;
        const float* Bsb = smf + st * GST + A_ST;
#pragma unroll
        for (int ks = 0; ks < 4; ks++) {
            const int k0 = ks * 8;
            uint32_t a[2][4];
#pragma unroll
            for (int mt = 0; mt < 2; mt++) {
                const int mr = wm * 32 + mt * 16;
                a[mt][0] = __float_as_uint(Asb[(mr + gid) * APAD + k0 + tig]);
                a[mt][1] = __float_as_uint(Asb[(mr + gid + 8) * APAD + k0 + tig]);
                a[mt][2] = __float_as_uint(Asb[(mr + gid) * APAD + k0 + tig + 4]);
                a[mt][3] = __float_as_uint(Asb[(mr + gid + 8) * APAD + k0 + tig + 4]);
            }
            uint32_t b[8][2];
#pragma unroll
            for (int nt = 0; nt < 8; nt++) {
                const int nc = wn * 64 + nt * 8 + gid;
                b[nt][0] = __float_as_uint(Bsb[(k0 + tig) * BPAD + nc]);
                b[nt][1] = __float_as_uint(Bsb[(k0 + tig + 4) * BPAD + nc]);
            }
#pragma unroll
            for (int mt = 0; mt < 2; mt++)
#pragma unroll
                for (int nt = 0; nt < 8; nt++)
                    mma_tf32(acc[mt][nt], a[mt], b[nt]);
        }
        st++; if (st == 3) st = 0;
    }

    // Epilogue with fused RoPE (pairs are (even,odd) columns = acc[..][0/1]).
    const int cm = blockIdx.y * 128 + wm * 32;
    const int cn = nTile * 128 + wn * 64;
#pragma unroll
    for (int mt = 0; mt < 2; mt++) {
        const int r0 = cm + mt * 16 + gid;
        const int r1 = r0 + 8;
#pragma unroll
        for (int nt = 0; nt < 8; nt++) {
            const int col = cn + nt * 8 + 2 * tig;
            float* p0 = C + (size_t)r0 * Ntot + col;
            float* p1 = C + (size_t)r1 * Ntot + col;
            if (doRope) {
                const int p  = (col >> 1) & 31;
                const int n0 = r0 & (NSEQ - 1);
                const int n1 = r1 & (NSEQ - 1);
                float c0 = fc[n0 * 32 + p], s0 = fs[n0 * 32 + p];
                float c1 = fc[n1 * 32 + p], s1 = fs[n1 * 32 + p];
                float xr0 = acc[mt][nt][0], xi0 = acc[mt][nt][1];
                float xr1 = acc[mt][nt][2], xi1 = acc[mt][nt][3];
                *(float2*)p0 = make_float2(roundtf(xr0 * c0 - xi0 * s0),
                                           roundtf(xr0 * s0 + xi0 * c0));
                *(float2*)p1 = make_float2(roundtf(xr1 * c1 - xi1 * s1),
                                           roundtf(xr1 * s1 + xi1 * c1));
            } else {
                *(float2*)p0 = make_float2(roundtf(acc[mt][nt][0]),
                                           roundtf(acc[mt][nt][1]));
                *(float2*)p1 = make_float2(roundtf(acc[mt][nt][2]),
                                           roundtf(acc[mt][nt][3]));
            }
        }
    }
}

// Plain GEMM for the output projection (BK=32, 3-stage, 256 threads).
__global__ __launch_bounds__(256, 2) void tf32gemm(
    const float* __restrict__ A, const float* __restrict__ B,
    float* __restrict__ C, int M, int N, int K)
{
    extern __shared__ float smf[];

    const int tid  = threadIdx.x;
    const int lane = tid & 31;
    const int wid  = tid >> 5;
    const int wm   = wid & 3;
    const int wn   = wid >> 2;
    const int gid  = lane >> 2;
    const int tig  = lane & 3;

    const float* Ab = A + (size_t)(blockIdx.y * 128) * K;
    const float* Bb = B + blockIdx.x * 128;

    auto load_stage = [&](int kt, int s) {
        float* Ad = smf + s * GST;
        float* Bd = smf + s * GST + A_ST;
        const int k0 = kt * 32;
#pragma unroll
        for (int i = 0; i < 4; i++) {
            int c = tid + i * 256;
            int ar = c >> 3, akq = (c & 7) << 2;
            cp_async16(Ad + ar * APAD + akq, Ab + (size_t)ar * K + k0 + akq);
            int br = c >> 5, bnq = (c & 31) << 2;
            cp_async16(Bd + br * BPAD + bnq, Bb + (size_t)(k0 + br) * N + bnq);
        }
    };

    float acc[2][8][4];
#pragma unroll
    for (int mt = 0; mt < 2; mt++)
#pragma unroll
        for (int nt = 0; nt < 8; nt++)
#pragma unroll
            for (int i = 0; i < 4; i++) acc[mt][nt][i] = 0.f;

    const int nk = K / 32;
    load_stage(0, 0); CP_COMMIT();
    load_stage(1, 1); CP_COMMIT();

    int st = 0;
    for (int kt = 0; kt < nk; kt++) {
        if (kt < nk - 1) { CP_WAIT1(); } else { CP_WAIT0(); }
        __syncthreads();

        if (kt + 2 < nk) {
            int s2 = st + 2; if (s2 >= 3) s2 -= 3;
            load_stage(kt + 2, s2);
            CP_COMMIT();
        }

        const float* Asb = smf + st * GST;
        const float* Bsb = smf + st * GST + A_ST;
#pragma unroll
        for (int ks = 0; ks < 4; ks++) {
            const int k0 = ks * 8;
            uint32_t a[2][4];
#pragma unroll
            for (int mt = 0; mt < 2; mt++) {
                const int mr = wm * 32 + mt * 16;
                a[mt][0] = __float_as_uint(Asb[(mr + gid) * APAD + k0 + tig]);
                a[mt][1] = __float_as_uint(Asb[(mr + gid + 8) * APAD + k0 + tig]);
                a[mt][2] = __float_as_uint(Asb[(mr + gid) * APAD + k0 + tig + 4]);
                a[mt][3] = __float_as_uint(Asb[(mr + gid + 8) * APAD + k0 + tig + 4]);
            }
            uint32_t b[8][2];
#pragma unroll
            for (int nt = 0; nt < 8; nt++) {
                const int nc = wn * 64 + nt * 8 + gid;
                b[nt][0] = __float_as_uint(Bsb[(k0 + tig) * BPAD + nc]);
                b[nt][1] = __float_as_uint(Bsb[(k0 + tig + 4) * BPAD + nc]);
            }
#pragma unroll
            for (int mt = 0; mt < 2; mt++)
#pragma unroll
                for (int nt = 0; nt < 8; nt++)
                    mma_tf32(acc[mt][nt], a[mt], b[nt]);
        }
        st++; if (st == 3) st = 0;
    }

    const int cm = blockIdx.y * 128 + wm * 32;
    const int cn = blockIdx.x * 128 + wn * 64;
#pragma unroll
    for (int mt = 0; mt < 2; mt++) {
#pragma unroll
        for (int nt = 0; nt < 8; nt++) {
            float* p0 = C + (size_t)(cm + mt * 16 + gid) * N + cn + nt * 8 + 2 * tig;
            float* p1 = p0 + (size_t)8 * N;
            *(float2*)p0 = make_float2(acc[mt][nt][0], acc[mt][nt][1]);
            *(float2*)p1 = make_float2(acc[mt][nt][2], acc[mt][nt][3]);
        }
    }
}

// ---------------------------------------------------------------------------
// Tensor-core flash attention (tf32), causal, GQA. LPT schedule.
// P staging reuses the just-consumed K stage buffer (dead after QK) ->
// no dedicated sP region -> 71.7 KB smem -> 3 CTAs/SM (smem/reg determined;
// no forced min-blocks directive).
// ---------------------------------------------------------------------------
#define KPITCH 68
#define VPITCH 72
#define PPITCH 68                       // == KPITCH (P slice fits K stage)
#define KBUF (64 * KPITCH)              // 4352 floats = 4 warps * 16*68
#define VBUF (64 * VPITCH)
#define SMEM_ATTN ((2 * KBUF + 2 * VBUF) * 4)   // 71680 bytes

__global__ __launch_bounds__(128) void attn_tc(
    const float* __restrict__ Q, const float* __restrict__ Kg,
    const float* __restrict__ Vg, float* __restrict__ O)
{
    extern __shared__ char smem_raw[];
    float* sK = (float*)smem_raw;
    float* sV = (float*)(smem_raw + 2 * KBUF * 4);

    const int qt = NQT - 1 - blockIdx.x;   // LPT: big tiles first
    const int h = blockIdx.y, b = blockIdx.z;
    const int kvh = h >> 2;
    const int tid = threadIdx.x;
    const int w = tid >> 5;
    const int lane = tid & 31;
    const int gid = lane >> 2, tig = lane & 3;

    const int qr0 = qt * 64 + w * 16 + gid;
    const int qr1 = qr0 + 8;

    uint32_t aq[8][4];
    {
        const float* q0 = Q + ((size_t)(b * NSEQ) + qr0) * DMODEL + h * HD;
        const float* q1 = Q + ((size_t)(b * NSEQ) + qr1) * DMODEL + h * HD;
#pragma unroll
        for (int ks = 0; ks < 8; ks++) {
            int d = ks * 8 + tig;
            aq[ks][0] = __float_as_uint(q0[d] * 0.125f);
            aq[ks][1] = __float_as_uint(q1[d] * 0.125f);
            aq[ks][2] = __float_as_uint(q0[d + 4] * 0.125f);
            aq[ks][3] = __float_as_uint(q1[d + 4] * 0.125f);
        }
    }

    float o[8][4];
#pragma unroll
    for (int nt = 0; nt < 8; nt++)
#pragma unroll
        for (int i = 0; i < 4; i++) o[nt][i] = 0.f;
    float m0 = -1e30f, l0 = 0.f, m1 = -1e30f, l1 = 0.f;

    const size_t kvs = NKVH * HD;

    auto load_tile = [&](int t, int st) {
        const float* kb = Kg + (size_t)(b * NSEQ + t * 64) * kvs + kvh * HD;
        const float* vb = Vg + (size_t)(b * NSEQ + t * 64) * kvs + kvh * HD;
        float* dK = sK + st * KBUF;
        float* dV = sV + st * VBUF;
#pragma unroll
        for (int i = 0; i < 8; i++) {
            int c = tid + i * 128;
            int r = c >> 4, c4 = (c & 15) << 2;
            cp_async16(dK + r * KPITCH + c4, kb + (size_t)r * kvs + c4);
            cp_async16(dV + r * VPITCH + c4, vb + (size_t)r * kvs + c4);
        }
    };

    load_tile(0, 0);
    CP_COMMIT();

    for (int t = 0; t <= qt; t++) {
        const int st = t & 1;
        CP_WAIT0();
        __syncthreads();

        if (t < qt) { load_tile(t + 1, st ^ 1); CP_COMMIT(); }

        const float* bK = sK + st * KBUF;
        const float* bV = sV + st * VBUF;

        float s[8][4];
#pragma unroll
        for (int nt = 0; nt < 8; nt++)
#pragma unroll
            for (int i = 0; i < 4; i++) s[nt][i] = 0.f;
#pragma unroll
        for (int ks = 0; ks < 8; ks++) {
            const int d0 = ks * 8;
#pragma unroll
            for (int nt = 0; nt < 8; nt++) {
                const float* kr = bK + (nt * 8 + gid) * KPITCH + d0 + tig;
                uint32_t bb[2];
                bb[0] = __float_as_uint(kr[0]);
                bb[1] = __float_as_uint(kr[4]);
                mma_tf32(s[nt], aq[ks], bb);
            }
        }

        if (t == qt) {
#pragma unroll
            for (int nt = 0; nt < 8; nt++) {
                int k0 = nt * 8 + 2 * tig;
                int r0 = w * 16 + gid;
                if (k0 > r0)         s[nt][0] = -1e30f;
                if (k0 + 1 > r0)     s[nt][1] = -1e30f;
                if (k0 > r0 + 8)     s[nt][2] = -1e30f;
                if (k0 + 1 > r0 + 8) s[nt][3] = -1e30f;
            }
        }

        float mx0 = -1e30f, mx1 = -1e30f;
#pragma unroll
        for (int nt = 0; nt < 8; nt++) {
            mx0 = fmaxf(mx0, fmaxf(s[nt][0], s[nt][1]));
            mx1 = fmaxf(mx1, fmaxf(s[nt][2], s[nt][3]));
        }
        mx0 = fmaxf(mx0, __shfl_xor_sync(0xffffffffu, mx0, 1));
        mx0 = fmaxf(mx0, __shfl_xor_sync(0xffffffffu, mx0, 2));
        mx1 = fmaxf(mx1, __shfl_xor_sync(0xffffffffu, mx1, 1));
        mx1 = fmaxf(mx1, __shfl_xor_sync(0xffffffffu, mx1, 2));

        float mn0 = fmaxf(m0, mx0), mn1 = fmaxf(m1, mx1);
        float c0 = __expf(m0 - mn0), c1 = __expf(m1 - mn1);
        float ls0 = 0.f, ls1 = 0.f;
#pragma unroll
        for (int nt = 0; nt < 8; nt++) {
            s[nt][0] = __expf(s[nt][0] - mn0);
            s[nt][1] = __expf(s[nt][1] - mn0);
            s[nt][2] = __expf(s[nt][2] - mn1);
            s[nt][3] = __expf(s[nt][3] - mn1);
            ls0 += s[nt][0] + s[nt][1];
            ls1 += s[nt][2] + s[nt][3];
        }
        ls0 += __shfl_xor_sync(0xffffffffu, ls0, 1);
        ls0 += __shfl_xor_sync(0xffffffffu, ls0, 2);
        ls1 += __shfl_xor_sync(0xffffffffu, ls1, 1);
        ls1 += __shfl_xor_sync(0xffffffffu, ls1, 2);
        l0 = l0 * c0 + ls0;
        l1 = l1 * c1 + ls1;
        m0 = mn0; m1 = mn1;
#pragma unroll
        for (int nt = 0; nt < 8; nt++) {
            o[nt][0] *= c0; o[nt][1] *= c0;
            o[nt][2] *= c1; o[nt][3] *= c1;
        }

        // All warps must be done reading K stage st before P overwrites it.
        __syncthreads();

        // P -> per-warp slice inside the dead K stage buffer (tf32 bits).
        uint32_t* pw = (uint32_t*)(sK + st * KBUF) + w * (16 * PPITCH);
#pragma unroll
        for (int nt = 0; nt < 8; nt++) {
            uint2 v0 = make_uint2(f2tf32(s[nt][0]), f2tf32(s[nt][1]));
            uint2 v1 = make_uint2(f2tf32(s[nt][2]), f2tf32(s[nt][3]));
            *(uint2*)(pw + gid * PPITCH + nt * 8 + 2 * tig) = v0;
            *(uint2*)(pw + (gid + 8) * PPITCH + nt * 8 + 2 * tig) = v1;
        }
        __syncwarp();

#pragma unroll
        for (int ks = 0; ks < 8; ks++) {
            const int k0 = ks * 8;
            uint32_t ap[4];
            ap[0] = pw[gid * PPITCH + k0 + tig];
            ap[1] = pw[(gid + 8) * PPITCH + k0 + tig];
            ap[2] = pw[gid * PPITCH + k0 + tig + 4];
            ap[3] = pw[(gid + 8) * PPITCH + k0 + tig + 4];
#pragma unroll
            for (int nt = 0; nt < 8; nt++) {
                const float* vr = bV + (k0 + tig) * VPITCH + nt * 8 + gid;
                uint32_t bb[2];
                bb[0] = __float_as_uint(vr[0]);
                bb[1] = __float_as_uint(vr[4 * VPITCH]);
                mma_tf32(o[nt], ap, bb);
            }
        }
    }

    float inv0 = 1.f / l0, inv1 = 1.f / l1;
    float* o0 = O + ((size_t)(b * NSEQ) + qr0) * DMODEL + h * HD;
    float* o1 = O + ((size_t)(b * NSEQ) + qr1) * DMODEL + h * HD;
#pragma unroll
    for (int nt = 0; nt < 8; nt++) {
        *(float2*)(o0 + nt * 8 + 2 * tig) =
            make_float2(roundtf(o[nt][0] * inv0), roundtf(o[nt][1] * inv0));
        *(float2*)(o1 + nt * 8 + 2 * tig) =
            make_float2(roundtf(o[nt][2] * inv1), roundtf(o[nt][3] * inv1));
    }
}

// ---------------------------------------------------------------------------
// Launch. Order: round_all(1), qkv(2), attn(3), O-gemm(4 = ncu slot).
// ---------------------------------------------------------------------------
extern "C" void kernel_launch(void* const* d_in, const int* in_sizes, int n_in,
                              void* d_out, int out_size)
{
    const float* x  = (const float*)d_in[0];
    const float* Wq = (const float*)d_in[1];
    const float* Wk = (const float*)d_in[2];
    const float* Wv = (const float*)d_in[3];
    const float* Wo = (const float*)d_in[4];
    const float* fc = (const float*)d_in[5];
    const float* fs = (const float*)d_in[6];
    float* out = (float*)d_out;

    float *Qp, *Kp, *Vp, *Op, *xr, *Wqr, *Wkr, *Wvr, *Wor;
    cudaGetSymbolAddress((void**)&Qp,  g_Q);
    cudaGetSymbolAddress((void**)&Kp,  g_K);
    cudaGetSymbolAddress((void**)&Vp,  g_V);
    cudaGetSymbolAddress((void**)&Op,  g_O);
    cudaGetSymbolAddress((void**)&xr,  g_xr);
    cudaGetSymbolAddress((void**)&Wqr, g_Wqr);
    cudaGetSymbolAddress((void**)&Wkr, g_Wkr);
    cudaGetSymbolAddress((void**)&Wvr, g_Wvr);
    cudaGetSymbolAddress((void**)&Wor, g_Wor);

    static bool attr_set = false;
    if (!attr_set) {
        cudaFuncSetAttribute(attn_tc,
            cudaFuncAttributeMaxDynamicSharedMemorySize, SMEM_ATTN);
        cudaFuncSetAttribute(qkv_gemm,
            cudaFuncAttributeMaxDynamicSharedMemorySize, GEMM_DYN);
        cudaFuncSetAttribute(tf32gemm,
            cudaFuncAttributeMaxDynamicSharedMemorySize, GEMM_DYN);
        attr_set = true;
    }

    // 1: fused tf32 rounding
    round_all<<<(N4_ALL + 255) / 256, 256>>>(
        (const float4*)x, (const float4*)Wq, (const float4*)Wk,
        (const float4*)Wv, (const float4*)Wo,
        (float4*)xr, (float4*)Wqr, (float4*)Wkr, (float4*)Wvr, (float4*)Wor);

    // 2: fused Q/K/V projection + RoPE (256-thread CTAs, R9 config)
    qkv_gemm<<<dim3(24, ROWS / 128), 256, GEMM_DYN>>>(
        xr, Wqr, Wkr, Wvr, Qp, Kp, Vp, fc, fs);

    // 3: attention (LPT-ordered, 3 CTAs/SM via reduced smem)
    attn_tc<<<dim3(NQT, NH, BATCH), 128, SMEM_ATTN>>>(Qp, Kp, Vp, Op);

    // 4: output projection  <-- ncu capture slot
    tf32gemm<<<dim3(DMODEL / 128, ROWS / 128), 256, GEMM_DYN>>>(
        Op, Wor, out, ROWS, DMODEL, DMODEL);
}

// round 14
// speedup vs baseline: 1.1205x; 1.0566x over previous
#include <cuda_runtime.h>
#include <math.h>
#include <stdint.h>

// Problem constants
#define BATCH 2
#define NSEQ  2048
#define DMODEL 2048
#define NH    32
#define NKVH  8
#define HD    64
#define ROWS  4096       // BATCH * NSEQ
#define NQT   (NSEQ / 64)   // 32 q-tiles

// ---------------------------------------------------------------------------
// Scratch (device globals -- no allocation allowed anywhere)
// ---------------------------------------------------------------------------
__device__ float g_Q[(size_t)ROWS * DMODEL];
__device__ float g_K[(size_t)ROWS * (NKVH * HD)];
__device__ float g_V[(size_t)ROWS * (NKVH * HD)];
__device__ float g_O[(size_t)ROWS * DMODEL];
__device__ float g_xr[(size_t)ROWS * DMODEL];
__device__ float g_Wqr[(size_t)DMODEL * DMODEL];
__device__ float g_Wkr[(size_t)DMODEL * (NKVH * HD)];
__device__ float g_Wvr[(size_t)DMODEL * (NKVH * HD)];
__device__ float g_Wor[(size_t)DMODEL * DMODEL];

// ---------------------------------------------------------------------------
// Helpers
// ---------------------------------------------------------------------------
__device__ __forceinline__ void cp_async16(void* smem, const void* gmem) {
    uint32_t s = (uint32_t)__cvta_generic_to_shared(smem);
    asm volatile("cp.async.cg.shared.global [%0], [%1], 16;\n" ::"r"(s), "l"(gmem));
}
#define CP_COMMIT() asm volatile("cp.async.commit_group;\n" ::: "memory")
#define CP_WAIT0()  asm volatile("cp.async.wait_group 0;\n" ::: "memory")
#define CP_WAIT1()  asm volatile("cp.async.wait_group 1;\n" ::: "memory")

__device__ __forceinline__ uint32_t f2tf32(float x) {
    uint32_t r;
    asm("cvt.rna.tf32.f32 %0, %1;" : "=r"(r) : "f"(x));
    return r;
}
__device__ __forceinline__ float roundtf(float x) {
    return __uint_as_float(f2tf32(x));
}

__device__ __forceinline__ void mma_tf32(float* c, const uint32_t* a, const uint32_t* b) {
    asm volatile(
        "mma.sync.aligned.m16n8k8.row.col.f32.tf32.tf32.f32 "
        "{%0,%1,%2,%3}, {%4,%5,%6,%7}, {%8,%9}, {%0,%1,%2,%3};"
        : "+f"(c[0]), "+f"(c[1]), "+f"(c[2]), "+f"(c[3])
        : "r"(a[0]), "r"(a[1]), "r"(a[2]), "r"(a[3]), "r"(b[0]), "r"(b[1]));
}

// ldmatrix x4: four 8x8 b16 tiles (= 8 rows x 16B each); lanes 0-7/8-15/16-23/24-31
// supply the row addresses of tiles 0/1/2/3 -> regs r[0..3].
__device__ __forceinline__ void ldsm_x4(uint32_t* r, uint32_t smem_addr) {
    asm volatile(
        "ldmatrix.sync.aligned.m8n8.x4.shared.b16 {%0,%1,%2,%3}, [%4];"
        : "=r"(r[0]), "=r"(r[1]), "=r"(r[2]), "=r"(r[3]) : "r"(smem_addr));
}

// ---------------------------------------------------------------------------
// Fused tf32 rounding of x and all weights (one launch).
// ---------------------------------------------------------------------------
#define N4_X   ((ROWS * DMODEL) / 4)
#define N4_WQ  ((DMODEL * DMODEL) / 4)
#define N4_WKV ((DMODEL * NKVH * HD) / 4)
#define N4_ALL (N4_X + N4_WQ + 2 * N4_WKV + N4_WQ)

__global__ void round_all(const float4* __restrict__ x,
                          const float4* __restrict__ Wq,
                          const float4* __restrict__ Wk,
                          const float4* __restrict__ Wv,
                          const float4* __restrict__ Wo,
                          float4* __restrict__ xr,
                          float4* __restrict__ Wqr,
                          float4* __restrict__ Wkr,
                          float4* __restrict__ Wvr,
                          float4* __restrict__ Wor)
{
    int i = blockIdx.x * blockDim.x + threadIdx.x;
    if (i >= N4_ALL) return;
    const float4* src;
    float4* dst;
    int j = i;
    if (j < N4_X) { src = x; dst = xr; }
    else {
        j -= N4_X;
        if (j < N4_WQ) { src = Wq; dst = Wqr; }
        else {
            j -= N4_WQ;
            if (j < N4_WKV) { src = Wk; dst = Wkr; }
            else {
                j -= N4_WKV;
                if (j < N4_WKV) { src = Wv; dst = Wvr; }
                else { j -= N4_WKV; src = Wo; dst = Wor; }
            }
        }
    }
    float4 v = src[j];
    dst[j] = make_float4(roundtf(v.x), roundtf(v.y), roundtf(v.z), roundtf(v.w));
}

// ---------------------------------------------------------------------------
// GEMM tiling (R9 config): block 128x128, BK=32, 3-stage cp.async,
// 256 threads (8 warps, 4m x 2n, warp tile 32x64). A-frags via ldmatrix.
// ---------------------------------------------------------------------------
#define APAD 36
#define BPAD 136
#define A_ST (128 * APAD)                 // 4608 floats
#define B_ST (32 * BPAD)                  // 4352 floats
#define GST  (A_ST + B_ST)                // 8960 floats per stage
#define GEMM_DYN (3 * GST * 4)            // 107520 bytes

// Fused QKV projection + RoPE epilogue.
__global__ __launch_bounds__(256, 2) void qkv_gemm(
    const float* __restrict__ A,
    const float* __restrict__ Wq, const float* __restrict__ Wk,
    const float* __restrict__ Wv,
    float* __restrict__ Qo, float* __restrict__ Ko, float* __restrict__ Vo,
    const float* __restrict__ fc, const float* __restrict__ fs)
{
    extern __shared__ float smf[];
    const uint32_t smf_u = (uint32_t)__cvta_generic_to_shared(smf);

    const int tid  = threadIdx.x;
    const int lane = tid & 31;
    const int wid  = tid >> 5;
    const int wm   = wid & 3;
    const int wn   = wid >> 2;
    const int gid  = lane >> 2;
    const int tig  = lane & 3;
    const int bx   = blockIdx.x;

    // ldmatrix A address pattern (per lane): tiles (r0..7,k0),(r8..15,k0),(r0..7,k0+4),(r8..15,k0+4)
    const int arow = (lane & 7) + (((lane >> 3) & 1) << 3);
    const int acol = (lane >> 4) << 2;

    const float* B;
    float* C;
    int nTile, Ntot, doRope;
    if (bx < 16)      { B = Wq; C = Qo; nTile = bx;      Ntot = DMODEL;    doRope = 1; }
    else if (bx < 20) { B = Wk; C = Ko; nTile = bx - 16; Ntot = NKVH * HD; doRope = 1; }
    else              { B = Wv; C = Vo; nTile = bx - 20; Ntot = NKVH * HD; doRope = 0; }

    const int K = DMODEL;
    const float* Ab = A + (size_t)(blockIdx.y * 128) * K;
    const float* Bb = B + nTile * 128;

    auto load_stage = [&](int kt, int s) {
        float* Ad = smf + s * GST;
        float* Bd = smf + s * GST + A_ST;
        const int k0 = kt * 32;
#pragma unroll
        for (int i = 0; i < 4; i++) {
            int c = tid + i * 256;
            int ar = c >> 3, akq = (c & 7) << 2;
            cp_async16(Ad + ar * APAD + akq, Ab + (size_t)ar * K + k0 + akq);
            int br = c >> 5, bnq = (c & 31) << 2;
            cp_async16(Bd + br * BPAD + bnq, Bb + (size_t)(k0 + br) * Ntot + bnq);
        }
    };

    float acc[2][8][4];
#pragma unroll
    for (int mt = 0; mt < 2; mt++)
#pragma unroll
        for (int nt = 0; nt < 8; nt++)
#pragma unroll
            for (int i = 0; i < 4; i++) acc[mt][nt][i] = 0.f;

    const int nk = K / 32;   // 64
    load_stage(0, 0); CP_COMMIT();
    load_stage(1, 1); CP_COMMIT();

    int st = 0;
    for (int kt = 0; kt < nk; kt++) {
        if (kt < nk - 1) { CP_WAIT1(); } else { CP_WAIT0(); }
        __syncthreads();

        if (kt + 2 < nk) {
            int s2 = st + 2; if (s2 >= 3) s2 -= 3;
            load_stage(kt + 2, s2);
            CP_COMMIT();
        }

        const uint32_t asb_u = smf_u + (uint32_t)(st * GST) * 4u;
        const float* Bsb = smf + st * GST + A_ST;
#pragma unroll
        for (int ks = 0; ks < 4; ks++) {
            const int k0 = ks * 8;
            uint32_t a[2][4];
#pragma unroll
            for (int mt = 0; mt < 2; mt++) {
                const int mr = wm * 32 + mt * 16;
                ldsm_x4(a[mt], asb_u + (uint32_t)((mr + arow) * APAD + k0 + acol) * 4u);
            }
            uint32_t b[8][2];
#pragma unroll
            for (int nt = 0; nt < 8; nt++) {
                const int nc = wn * 64 + nt * 8 + gid;
                b[nt][0] = __float_as_uint(Bsb[(k0 + tig) * BPAD + nc]);
                b[nt][1] = __float_as_uint(Bsb[(k0 + tig + 4) * BPAD + nc]);
            }
#pragma unroll
            for (int mt = 0; mt < 2; mt++)
#pragma unroll
                for (int nt = 0; nt < 8; nt++)
                    mma_tf32(acc[mt][nt], a[mt], b[nt]);
        }
        st++; if (st == 3) st = 0;
    }

    // Epilogue with fused RoPE (pairs are (even,odd) columns = acc[..][0/1]).
    const int cm = blockIdx.y * 128 + wm * 32;
    const int cn = nTile * 128 + wn * 64;
#pragma unroll
    for (int mt = 0; mt < 2; mt++) {
        const int r0 = cm + mt * 16 + gid;
        const int r1 = r0 + 8;
#pragma unroll
        for (int nt = 0; nt < 8; nt++) {
            const int col = cn + nt * 8 + 2 * tig;
            float* p0 = C + (size_t)r0 * Ntot + col;
            float* p1 = C + (size_t)r1 * Ntot + col;
            if (doRope) {
                const int p  = (col >> 1) & 31;
                const int n0 = r0 & (NSEQ - 1);
                const int n1 = r1 & (NSEQ - 1);
                float c0 = fc[n0 * 32 + p], s0 = fs[n0 * 32 + p];
                float c1 = fc[n1 * 32 + p], s1 = fs[n1 * 32 + p];
                float xr0 = acc[mt][nt][0], xi0 = acc[mt][nt][1];
                float xr1 = acc[mt][nt][2], xi1 = acc[mt][nt][3];
                *(float2*)p0 = make_float2(roundtf(xr0 * c0 - xi0 * s0),
                                           roundtf(xr0 * s0 + xi0 * c0));
                *(float2*)p1 = make_float2(roundtf(xr1 * c1 - xi1 * s1),
                                           roundtf(xr1 * s1 + xi1 * c1));
            } else {
                *(float2*)p0 = make_float2(roundtf(acc[mt][nt][0]),
                                           roundtf(acc[mt][nt][1]));
                *(float2*)p1 = make_float2(roundtf(acc[mt][nt][2]),
                                           roundtf(acc[mt][nt][3]));
            }
        }
    }
}

// Plain GEMM for the output projection (BK=32, 3-stage, 256 threads).
__global__ __launch_bounds__(256, 2) void tf32gemm(
    const float* __restrict__ A, const float* __restrict__ B,
    float* __restrict__ C, int M, int N, int K)
{
    extern __shared__ float smf[];
    const uint32_t smf_u = (uint32_t)__cvta_generic_to_shared(smf);

    const int tid  = threadIdx.x;
    const int lane = tid & 31;
    const int wid  = tid >> 5;
    const int wm   = wid & 3;
    const int wn   = wid >> 2;
    const int gid  = lane >> 2;
    const int tig  = lane & 3;

    const int arow = (lane & 7) + (((lane >> 3) & 1) << 3);
    const int acol = (lane >> 4) << 2;

    const float* Ab = A + (size_t)(blockIdx.y * 128) * K;
    const float* Bb = B + blockIdx.x * 128;

    auto load_stage = [&](int kt, int s) {
        float* Ad = smf + s * GST;
        float* Bd = smf + s * GST + A_ST;
        const int k0 = kt * 32;
#pragma unroll
        for (int i = 0; i < 4; i++) {
            int c = tid + i * 256;
            int ar = c >> 3, akq = (c & 7) << 2;
            cp_async16(Ad + ar * APAD + akq, Ab + (size_t)ar * K + k0 + akq);
            int br = c >> 5, bnq = (c & 31) << 2;
            cp_async16(Bd + br * BPAD + bnq, Bb + (size_t)(k0 + br) * N + bnq);
        }
    };

    float acc[2][8][4];
#pragma unroll
    for (int mt = 0; mt < 2; mt++)
#pragma unroll
        for (int nt = 0; nt < 8; nt++)
#pragma unroll
            for (int i = 0; i < 4; i++) acc[mt][nt][i] = 0.f;

    const int nk = K / 32;
    load_stage(0, 0); CP_COMMIT();
    load_stage(1, 1); CP_COMMIT();

    int st = 0;
    for (int kt = 0; kt < nk; kt++) {
        if (kt < nk - 1) { CP_WAIT1(); } else { CP_WAIT0(); }
        __syncthreads();

        if (kt + 2 < nk) {
            int s2 = st + 2; if (s2 >= 3) s2 -= 3;
            load_stage(kt + 2, s2);
            CP_COMMIT();
        }

        const uint32_t asb_u = smf_u + (uint32_t)(st * GST) * 4u;
        const float* Bsb = smf + st * GST + A_ST;
#pragma unroll
        for (int ks = 0; ks < 4; ks++) {
            const int k0 = ks * 8;
            uint32_t a[2][4];
#pragma unroll
            for (int mt = 0; mt < 2; mt++) {
                const int mr = wm * 32 + mt * 16;
                ldsm_x4(a[mt], asb_u + (uint32_t)((mr + arow) * APAD + k0 + acol) * 4u);
            }
            uint32_t b[8][2];
#pragma unroll
            for (int nt = 0; nt < 8; nt++) {
                const int nc = wn * 64 + nt * 8 + gid;
                b[nt][0] = __float_as_uint(Bsb[(k0 + tig) * BPAD + nc]);
                b[nt][1] = __float_as_uint(Bsb[(k0 + tig + 4) * BPAD + nc]);
            }
#pragma unroll
            for (int mt = 0; mt < 2; mt++)
#pragma unroll
                for (int nt = 0; nt < 8; nt++)
                    mma_tf32(acc[mt][nt], a[mt], b[nt]);
        }
        st++; if (st == 3) st = 0;
    }

    const int cm = blockIdx.y * 128 + wm * 32;
    const int cn = blockIdx.x * 128 + wn * 64;
#pragma unroll
    for (int mt = 0; mt < 2; mt++) {
#pragma unroll
        for (int nt = 0; nt < 8; nt++) {
            float* p0 = C + (size_t)(cm + mt * 16 + gid) * N + cn + nt * 8 + 2 * tig;
            float* p1 = p0 + (size_t)8 * N;
            *(float2*)p0 = make_float2(acc[mt][nt][0], acc[mt][nt][1]);
            *(float2*)p1 = make_float2(acc[mt][nt][2], acc[mt][nt][3]);
        }
    }
}

// ---------------------------------------------------------------------------
// Tensor-core flash attention (tf32), causal, GQA. LPT schedule.
// P staged in dead K buffer (3 CTAs/SM). K-frags and P-frags via ldmatrix.
// ---------------------------------------------------------------------------
#define KPITCH 68
#define VPITCH 72
#define PPITCH 68
#define KBUF (64 * KPITCH)
#define VBUF (64 * VPITCH)
#define SMEM_ATTN ((2 * KBUF + 2 * VBUF) * 4)   // 71680 bytes

__global__ __launch_bounds__(128) void attn_tc(
    const float* __restrict__ Q, const float* __restrict__ Kg,
    const float* __restrict__ Vg, float* __restrict__ O)
{
    extern __shared__ char smem_raw[];
    float* sK = (float*)smem_raw;
    float* sV = (float*)(smem_raw + 2 * KBUF * 4);
    const uint32_t sk_u = (uint32_t)__cvta_generic_to_shared(smem_raw);

    const int qt = NQT - 1 - blockIdx.x;   // LPT: big tiles first
    const int h = blockIdx.y, b = blockIdx.z;
    const int kvh = h >> 2;
    const int tid = threadIdx.x;
    const int w = tid >> 5;
    const int lane = tid & 31;
    const int gid = lane >> 2, tig = lane & 3;

    // ldmatrix address patterns
    const int qk_row = lane & 7;            // key within octet
    const int qk_col = (lane >> 3) << 2;    // d offset group (0,4,8,12)
    const int p_row  = (lane & 7) + (((lane >> 3) & 1) << 3);
    const int p_col  = (lane >> 4) << 2;

    const int qr0 = qt * 64 + w * 16 + gid;
    const int qr1 = qr0 + 8;

    uint32_t aq[8][4];
    {
        const float* q0 = Q + ((size_t)(b * NSEQ) + qr0) * DMODEL + h * HD;
        const float* q1 = Q + ((size_t)(b * NSEQ) + qr1) * DMODEL + h * HD;
#pragma unroll
        for (int ks = 0; ks < 8; ks++) {
            int d = ks * 8 + tig;
            aq[ks][0] = __float_as_uint(q0[d] * 0.125f);
            aq[ks][1] = __float_as_uint(q1[d] * 0.125f);
            aq[ks][2] = __float_as_uint(q0[d + 4] * 0.125f);
            aq[ks][3] = __float_as_uint(q1[d + 4] * 0.125f);
        }
    }

    float o[8][4];
#pragma unroll
    for (int nt = 0; nt < 8; nt++)
#pragma unroll
        for (int i = 0; i < 4; i++) o[nt][i] = 0.f;
    float m0 = -1e30f, l0 = 0.f, m1 = -1e30f, l1 = 0.f;

    const size_t kvs = NKVH * HD;

    auto load_tile = [&](int t, int st) {
        const float* kb = Kg + (size_t)(b * NSEQ + t * 64) * kvs + kvh * HD;
        const float* vb = Vg + (size_t)(b * NSEQ + t * 64) * kvs + kvh * HD;
        float* dK = sK + st * KBUF;
        float* dV = sV + st * VBUF;
#pragma unroll
        for (int i = 0; i < 8; i++) {
            int c = tid + i * 128;
            int r = c >> 4, c4 = (c & 15) << 2;
            cp_async16(dK + r * KPITCH + c4, kb + (size_t)r * kvs + c4);
            cp_async16(dV + r * VPITCH + c4, vb + (size_t)r * kvs + c4);
        }
    };

    load_tile(0, 0);
    CP_COMMIT();

    for (int t = 0; t <= qt; t++) {
        const int st = t & 1;
        CP_WAIT0();
        __syncthreads();

        if (t < qt) { load_tile(t + 1, st ^ 1); CP_COMMIT(); }

        const uint32_t bk_u = sk_u + (uint32_t)(st * KBUF) * 4u;
        const float* bV = sV + st * VBUF;

        // S = Q K^T via ldmatrix K-frags: one x4 covers d0..d0+15 (2 ks steps)
        float s[8][4];
#pragma unroll
        for (int nt = 0; nt < 8; nt++)
#pragma unroll
            for (int i = 0; i < 4; i++) s[nt][i] = 0.f;
#pragma unroll
        for (int ksp = 0; ksp < 4; ksp++) {
            const int d0 = ksp * 16;
#pragma unroll
            for (int nt = 0; nt < 8; nt++) {
                uint32_t bb4[4];
                ldsm_x4(bb4, bk_u +
                    (uint32_t)(((nt * 8 + qk_row) * KPITCH) + d0 + qk_col) * 4u);
                mma_tf32(s[nt], aq[2 * ksp],     bb4 + 0);
                mma_tf32(s[nt], aq[2 * ksp + 1], bb4 + 2);
            }
        }

        if (t == qt) {
#pragma unroll
            for (int nt = 0; nt < 8; nt++) {
                int k0 = nt * 8 + 2 * tig;
                int r0 = w * 16 + gid;
                if (k0 > r0)         s[nt][0] = -1e30f;
                if (k0 + 1 > r0)     s[nt][1] = -1e30f;
                if (k0 > r0 + 8)     s[nt][2] = -1e30f;
                if (k0 + 1 > r0 + 8) s[nt][3] = -1e30f;
            }
        }

        float mx0 = -1e30f, mx1 = -1e30f;
#pragma unroll
        for (int nt = 0; nt < 8; nt++) {
            mx0 = fmaxf(mx0, fmaxf(s[nt][0], s[nt][1]));
            mx1 = fmaxf(mx1, fmaxf(s[nt][2], s[nt][3]));
        }
        mx0 = fmaxf(mx0, __shfl_xor_sync(0xffffffffu, mx0, 1));
        mx0 = fmaxf(mx0, __shfl_xor_sync(0xffffffffu, mx0, 2));
        mx1 = fmaxf(mx1, __shfl_xor_sync(0xffffffffu, mx1, 1));
        mx1 = fmaxf(mx1, __shfl_xor_sync(0xffffffffu, mx1, 2));

        float mn0 = fmaxf(m0, mx0), mn1 = fmaxf(m1, mx1);
        float c0 = __expf(m0 - mn0), c1 = __expf(m1 - mn1);
        float ls0 = 0.f, ls1 = 0.f;
#pragma unroll
        for (int nt = 0; nt < 8; nt++) {
            s[nt][0] = __expf(s[nt][0] - mn0);
            s[nt][1] = __expf(s[nt][1] - mn0);
            s[nt][2] = __expf(s[nt][2] - mn1);
            s[nt][3] = __expf(s[nt][3] - mn1);
            ls0 += s[nt][0] + s[nt][1];
            ls1 += s[nt][2] + s[nt][3];
        }
        ls0 += __shfl_xor_sync(0xffffffffu, ls0, 1);
        ls0 += __shfl_xor_sync(0xffffffffu, ls0, 2);
        ls1 += __shfl_xor_sync(0xffffffffu, ls1, 1);
        ls1 += __shfl_xor_sync(0xffffffffu, ls1, 2);
        l0 = l0 * c0 + ls0;
        l1 = l1 * c1 + ls1;
        m0 = mn0; m1 = mn1;
#pragma unroll
        for (int nt = 0; nt < 8; nt++) {
            o[nt][0] *= c0; o[nt][1] *= c0;
            o[nt][2] *= c1; o[nt][3] *= c1;
        }

        // All warps must be done reading K stage st before P overwrites it.
        __syncthreads();

        // P -> per-warp slice inside the dead K stage buffer (tf32 bits).
        uint32_t* pw = (uint32_t*)(sK + st * KBUF) + w * (16 * PPITCH);
        const uint32_t pw_u = sk_u +
            (uint32_t)(st * KBUF + w * (16 * PPITCH)) * 4u;
#pragma unroll
        for (int nt = 0; nt < 8; nt++) {
            uint2 v0 = make_uint2(f2tf32(s[nt][0]), f2tf32(s[nt][1]));
            uint2 v1 = make_uint2(f2tf32(s[nt][2]), f2tf32(s[nt][3]));
            *(uint2*)(pw + gid * PPITCH + nt * 8 + 2 * tig) = v0;
            *(uint2*)(pw + (gid + 8) * PPITCH + nt * 8 + 2 * tig) = v1;
        }
        __syncwarp();

#pragma unroll
        for (int ks = 0; ks < 8; ks++) {
            const int k0 = ks * 8;
            uint32_t ap[4];
            ldsm_x4(ap, pw_u + (uint32_t)(p_row * PPITCH + k0 + p_col) * 4u);
#pragma unroll
            for (int nt = 0; nt < 8; nt++) {
                const float* vr = bV + (k0 + tig) * VPITCH + nt * 8 + gid;
                uint32_t bb[2];
                bb[0] = __float_as_uint(vr[0]);
                bb[1] = __float_as_uint(vr[4 * VPITCH]);
                mma_tf32(o[nt], ap, bb);
            }
        }
    }

    float inv0 = 1.f / l0, inv1 = 1.f / l1;
    float* o0 = O + ((size_t)(b * NSEQ) + qr0) * DMODEL + h * HD;
    float* o1 = O + ((size_t)(b * NSEQ) + qr1) * DMODEL + h * HD;
#pragma unroll
    for (int nt = 0; nt < 8; nt++) {
        *(float2*)(o0 + nt * 8 + 2 * tig) =
            make_float2(roundtf(o[nt][0] * inv0), roundtf(o[nt][1] * inv0));
        *(float2*)(o1 + nt * 8 + 2 * tig) =
            make_float2(roundtf(o[nt][2] * inv1), roundtf(o[nt][3] * inv1));
    }
}

// ---------------------------------------------------------------------------
// Launch. Order: round_all(1), qkv(2), attn(3), O-gemm(4 = ncu slot).
// ---------------------------------------------------------------------------
extern "C" void kernel_launch(void* const* d_in, const int* in_sizes, int n_in,
                              void* d_out, int out_size)
{
    const float* x  = (const float*)d_in[0];
    const float* Wq = (const float*)d_in[1];
    const float* Wk = (const float*)d_in[2];
    const float* Wv = (const float*)d_in[3];
    const float* Wo = (const float*)d_in[4];
    const float* fc = (const float*)d_in[5];
    const float* fs = (const float*)d_in[6];
    float* out = (float*)d_out;

    float *Qp, *Kp, *Vp, *Op, *xr, *Wqr, *Wkr, *Wvr, *Wor;
    cudaGetSymbolAddress((void**)&Qp,  g_Q);
    cudaGetSymbolAddress((void**)&Kp,  g_K);
    cudaGetSymbolAddress((void**)&Vp,  g_V);
    cudaGetSymbolAddress((void**)&Op,  g_O);
    cudaGetSymbolAddress((void**)&xr,  g_xr);
    cudaGetSymbolAddress((void**)&Wqr, g_Wqr);
    cudaGetSymbolAddress((void**)&Wkr, g_Wkr);
    cudaGetSymbolAddress((void**)&Wvr, g_Wvr);
    cudaGetSymbolAddress((void**)&Wor, g_Wor);

    static bool attr_set = false;
    if (!attr_set) {
        cudaFuncSetAttribute(attn_tc,
            cudaFuncAttributeMaxDynamicSharedMemorySize, SMEM_ATTN);
        cudaFuncSetAttribute(qkv_gemm,
            cudaFuncAttributeMaxDynamicSharedMemorySize, GEMM_DYN);
        cudaFuncSetAttribute(tf32gemm,
            cudaFuncAttributeMaxDynamicSharedMemorySize, GEMM_DYN);
        attr_set = true;
    }

    // 1: fused tf32 rounding
    round_all<<<(N4_ALL + 255) / 256, 256>>>(
        (const float4*)x, (const float4*)Wq, (const float4*)Wk,
        (const float4*)Wv, (const float4*)Wo,
        (float4*)xr, (float4*)Wqr, (float4*)Wkr, (float4*)Wvr, (float4*)Wor);

    // 2: fused Q/K/V projection + RoPE
    qkv_gemm<<<dim3(24, ROWS / 128), 256, GEMM_DYN>>>(
        xr, Wqr, Wkr, Wvr, Qp, Kp, Vp, fc, fs);

    // 3: attention (LPT-ordered, ldmatrix frags)
    attn_tc<<<dim3(NQT, NH, BATCH), 128, SMEM_ATTN>>>(Qp, Kp, Vp, Op);

    // 4: output projection  <-- ncu capture slot
    tf32gemm<<<dim3(DMODEL / 128, ROWS / 128), 256, GEMM_DYN>>>(
        Op, Wor, out, ROWS, DMODEL, DMODEL);
}

// round 17
// speedup vs baseline: 1.1304x; 1.0088x over previous
#include <cuda_runtime.h>
#include <math.h>
#include <stdint.h>

// Problem constants
#define BATCH 2
#define NSEQ  2048
#define DMODEL 2048
#define NH    32
#define NKVH  8
#define HD    64
#define ROWS  4096       // BATCH * NSEQ
#define NQT   (NSEQ / 64)   // 32 q-tiles

// ---------------------------------------------------------------------------
// Scratch (device globals -- no allocation allowed anywhere)
// ---------------------------------------------------------------------------
__device__ float g_Q[(size_t)ROWS * DMODEL];
__device__ float g_K[(size_t)ROWS * (NKVH * HD)];
__device__ float g_V[(size_t)ROWS * (NKVH * HD)];
__device__ float g_O[(size_t)ROWS * DMODEL];
__device__ float g_xr[(size_t)ROWS * DMODEL];
__device__ float g_Wqt[(size_t)DMODEL * DMODEL];         // [N,K] rounded
__device__ float g_Wkt[(size_t)(NKVH * HD) * DMODEL];
__device__ float g_Wvt[(size_t)(NKVH * HD) * DMODEL];
__device__ float g_Wot[(size_t)DMODEL * DMODEL];

// ---------------------------------------------------------------------------
// Helpers
// ---------------------------------------------------------------------------
__device__ __forceinline__ void cp_async16(void* smem, const void* gmem) {
    uint32_t s = (uint32_t)__cvta_generic_to_shared(smem);
    asm volatile("cp.async.cg.shared.global [%0], [%1], 16;\n" ::"r"(s), "l"(gmem));
}
#define CP_COMMIT() asm volatile("cp.async.commit_group;\n" ::: "memory")
#define CP_WAIT0()  asm volatile("cp.async.wait_group 0;\n" ::: "memory")
#define CP_WAIT1()  asm volatile("cp.async.wait_group 1;\n" ::: "memory")

__device__ __forceinline__ uint32_t f2tf32(float x) {
    uint32_t r;
    asm("cvt.rna.tf32.f32 %0, %1;" : "=r"(r) : "f"(x));
    return r;
}
__device__ __forceinline__ float roundtf(float x) {
    return __uint_as_float(f2tf32(x));
}

__device__ __forceinline__ void mma_tf32(float* c, const uint32_t* a, const uint32_t* b) {
    asm volatile(
        "mma.sync.aligned.m16n8k8.row.col.f32.tf32.tf32.f32 "
        "{%0,%1,%2,%3}, {%4,%5,%6,%7}, {%8,%9}, {%0,%1,%2,%3};"
        : "+f"(c[0]), "+f"(c[1]), "+f"(c[2]), "+f"(c[3])
        : "r"(a[0]), "r"(a[1]), "r"(a[2]), "r"(a[3]), "r"(b[0]), "r"(b[1]));
}

__device__ __forceinline__ void ldsm_x4(uint32_t* r, uint32_t smem_addr) {
    asm volatile(
        "ldmatrix.sync.aligned.m8n8.x4.shared.b16 {%0,%1,%2,%3}, [%4];"
        : "=r"(r[0]), "=r"(r[1]), "=r"(r[2]), "=r"(r[3]) : "r"(smem_addr));
}

// ---------------------------------------------------------------------------
// Prep 1: tf32-round x.
// ---------------------------------------------------------------------------
#define N4_X ((ROWS * DMODEL) / 4)

__global__ void round_x(const float4* __restrict__ x, float4* __restrict__ xr) {
    int i = blockIdx.x * blockDim.x + threadIdx.x;
    if (i >= N4_X) return;
    float4 v = x[i];
    xr[i] = make_float4(roundtf(v.x), roundtf(v.y), roundtf(v.z), roundtf(v.w));
}

// ---------------------------------------------------------------------------
// Prep 2: transpose+round all weights W[K,N] -> Wt[N,K] in one launch.
// grid (4096, 4); matrix m selects weight; extra tiles return early.
// ---------------------------------------------------------------------------
__global__ void tr_all(const float* __restrict__ Wq, const float* __restrict__ Wk,
                       const float* __restrict__ Wv, const float* __restrict__ Wo,
                       float* __restrict__ Wqt, float* __restrict__ Wkt,
                       float* __restrict__ Wvt, float* __restrict__ Wot)
{
    __shared__ float t[32][33];
    const int m = blockIdx.y;
    const float* W; float* Wt; int N;
    if (m == 0)      { W = Wq; Wt = Wqt; N = DMODEL; }
    else if (m == 1) { W = Wk; Wt = Wkt; N = NKVH * HD; }
    else if (m == 2) { W = Wv; Wt = Wvt; N = NKVH * HD; }
    else             { W = Wo; Wt = Wot; N = DMODEL; }

    const int tk = blockIdx.x & 63;       // K tile (K=2048 -> 64 tiles)
    const int tn = blockIdx.x >> 6;       // N tile
    if (tn >= (N >> 5)) return;

    const int tx = threadIdx.x & 31, ty = threadIdx.x >> 5;
#pragma unroll
    for (int i = 0; i < 4; i++)
        t[ty + i * 8][tx] = W[(size_t)(tk * 32 + ty + i * 8) * N + tn * 32 + tx];
    __syncthreads();
#pragma unroll
    for (int i = 0; i < 4; i++)
        Wt[(size_t)(tn * 32 + ty + i * 8) * DMODEL + tk * 32 + tx] =
            roundtf(t[tx][ty + i * 8]);
}

// ---------------------------------------------------------------------------
// GEMM: block 128x128, BK=32, 3-stage cp.async, 256 threads (4m x 2n warps,
// warp tile 32x64). BOTH operands K-major rows of 32 floats (A: [M,K] rows;
// B: Wt [N,K] rows) -> identical loaders, and both frag sets via ldmatrix.
// ---------------------------------------------------------------------------
#define GPITCH 36
#define OP_ST (128 * GPITCH)              // floats per operand stage (4608)
#define GST   (2 * OP_ST)                 // 9216 floats per stage
#define GEMM_DYN (3 * GST * 4)            // 110592 bytes

// Fused QKV projection + RoPE epilogue.
__global__ __launch_bounds__(256, 2) void qkv_gemm(
    const float* __restrict__ A,
    const float* __restrict__ Wq, const float* __restrict__ Wk,
    const float* __restrict__ Wv,
    float* __restrict__ Qo, float* __restrict__ Ko, float* __restrict__ Vo,
    const float* __restrict__ fc, const float* __restrict__ fs)
{
    extern __shared__ float smf[];
    const uint32_t smf_u = (uint32_t)__cvta_generic_to_shared(smf);

    const int tid  = threadIdx.x;
    const int lane = tid & 31;
    const int wid  = tid >> 5;
    const int wm   = wid & 3;
    const int wn   = wid >> 2;
    const int gid  = lane >> 2;
    const int tig  = lane & 3;
    const int bx   = blockIdx.x;

    // ldmatrix lane pattern (A and B identical): tile=lane>>3;
    // row = ((lane>>4)&1)*8 + (lane&7); col = ((lane>>3)&1)*4
    const int lrow = (lane & 7) + (((lane >> 4) & 1) << 3);
    const int lcol = ((lane >> 3) & 1) << 2;

    const float* B;
    float* C;
    int nTile, Ntot, doRope;
    if (bx < 16)      { B = Wq; C = Qo; nTile = bx;      Ntot = DMODEL;    doRope = 1; }
    else if (bx < 20) { B = Wk; C = Ko; nTile = bx - 16; Ntot = NKVH * HD; doRope = 1; }
    else              { B = Wv; C = Vo; nTile = bx - 20; Ntot = NKVH * HD; doRope = 0; }

    const int K = DMODEL;
    const float* Ab = A + (size_t)(blockIdx.y * 128) * K;
    const float* Bb = B + (size_t)(nTile * 128) * K;    // Wt rows (n-major)

    auto load_stage = [&](int kt, int s) {
        float* Ad = smf + s * GST;
        float* Bd = smf + s * GST + OP_ST;
        const int k0 = kt * 32;
#pragma unroll
        for (int i = 0; i < 4; i++) {
            int c = tid + i * 256;
            int r = c >> 3, kq = (c & 7) << 2;
            cp_async16(Ad + r * GPITCH + kq, Ab + (size_t)r * K + k0 + kq);
            cp_async16(Bd + r * GPITCH + kq, Bb + (size_t)r * K + k0 + kq);
        }
    };

    float acc[2][8][4];
#pragma unroll
    for (int mt = 0; mt < 2; mt++)
#pragma unroll
        for (int nt = 0; nt < 8; nt++)
#pragma unroll
            for (int i = 0; i < 4; i++) acc[mt][nt][i] = 0.f;

    const int nk = K / 32;   // 64
    load_stage(0, 0); CP_COMMIT();
    load_stage(1, 1); CP_COMMIT();

    int st = 0;
    for (int kt = 0; kt < nk; kt++) {
        if (kt < nk - 1) { CP_WAIT1(); } else { CP_WAIT0(); }
        __syncthreads();

        if (kt + 2 < nk) {
            int s2 = st + 2; if (s2 >= 3) s2 -= 3;
            load_stage(kt + 2, s2);
            CP_COMMIT();
        }

        const uint32_t asb_u = smf_u + (uint32_t)(st * GST) * 4u;
        const uint32_t bsb_u = asb_u + (uint32_t)OP_ST * 4u;
#pragma unroll
        for (int ks = 0; ks < 4; ks++) {
            const int k0 = ks * 8;
            uint32_t a[2][4];
#pragma unroll
            for (int mt = 0; mt < 2; mt++) {
                const int mr = wm * 32 + mt * 16;
                const int arow = (lane & 7) + (((lane >> 3) & 1) << 3);
                const int acol = (lane >> 4) << 2;
                ldsm_x4(a[mt], asb_u +
                        (uint32_t)((mr + arow) * GPITCH + k0 + acol) * 4u);
            }
            uint32_t b[8][2];
#pragma unroll
            for (int ntp = 0; ntp < 8; ntp += 2) {
                const int nr = wn * 64 + ntp * 8;
                uint32_t bb4[4];
                ldsm_x4(bb4, bsb_u +
                        (uint32_t)((nr + lrow) * GPITCH + k0 + lcol) * 4u);
                b[ntp][0] = bb4[0];     b[ntp][1] = bb4[1];
                b[ntp + 1][0] = bb4[2]; b[ntp + 1][1] = bb4[3];
            }
#pragma unroll
            for (int mt = 0; mt < 2; mt++)
#pragma unroll
                for (int nt = 0; nt < 8; nt++)
                    mma_tf32(acc[mt][nt], a[mt], b[nt]);
        }
        st++; if (st == 3) st = 0;
    }

    // Epilogue with fused RoPE (pairs are (even,odd) columns = acc[..][0/1]).
    const int cm = blockIdx.y * 128 + wm * 32;
    const int cn = nTile * 128 + wn * 64;
#pragma unroll
    for (int mt = 0; mt < 2; mt++) {
        const int r0 = cm + mt * 16 + gid;
        const int r1 = r0 + 8;
#pragma unroll
        for (int nt = 0; nt < 8; nt++) {
            const int col = cn + nt * 8 + 2 * tig;
            float* p0 = C + (size_t)r0 * Ntot + col;
            float* p1 = C + (size_t)r1 * Ntot + col;
            if (doRope) {
                const int p  = (col >> 1) & 31;
                const int n0 = r0 & (NSEQ - 1);
                const int n1 = r1 & (NSEQ - 1);
                float c0 = fc[n0 * 32 + p], s0 = fs[n0 * 32 + p];
                float c1 = fc[n1 * 32 + p], s1 = fs[n1 * 32 + p];
                float xr0 = acc[mt][nt][0], xi0 = acc[mt][nt][1];
                float xr1 = acc[mt][nt][2], xi1 = acc[mt][nt][3];
                *(float2*)p0 = make_float2(roundtf(xr0 * c0 - xi0 * s0),
                                           roundtf(xr0 * s0 + xi0 * c0));
                *(float2*)p1 = make_float2(roundtf(xr1 * c1 - xi1 * s1),
                                           roundtf(xr1 * s1 + xi1 * c1));
            } else {
                *(float2*)p0 = make_float2(roundtf(acc[mt][nt][0]),
                                           roundtf(acc[mt][nt][1]));
                *(float2*)p1 = make_float2(roundtf(acc[mt][nt][2]),
                                           roundtf(acc[mt][nt][3]));
            }
        }
    }
}

// Plain GEMM for the output projection (same structure, Bt = Wot [N,K]).
__global__ __launch_bounds__(256, 2) void tf32gemm(
    const float* __restrict__ A, const float* __restrict__ Bt,
    float* __restrict__ C, int M, int N, int K)
{
    extern __shared__ float smf[];
    const uint32_t smf_u = (uint32_t)__cvta_generic_to_shared(smf);

    const int tid  = threadIdx.x;
    const int lane = tid & 31;
    const int wid  = tid >> 5;
    const int wm   = wid & 3;
    const int wn   = wid >> 2;
    const int gid  = lane >> 2;
    const int tig  = lane & 3;

    const int lrow = (lane & 7) + (((lane >> 4) & 1) << 3);
    const int lcol = ((lane >> 3) & 1) << 2;

    const float* Ab = A  + (size_t)(blockIdx.y * 128) * K;
    const float* Bb = Bt + (size_t)(blockIdx.x * 128) * K;

    auto load_stage = [&](int kt, int s) {
        float* Ad = smf + s * GST;
        float* Bd = smf + s * GST + OP_ST;
        const int k0 = kt * 32;
#pragma unroll
        for (int i = 0; i < 4; i++) {
            int c = tid + i * 256;
            int r = c >> 3, kq = (c & 7) << 2;
            cp_async16(Ad + r * GPITCH + kq, Ab + (size_t)r * K + k0 + kq);
            cp_async16(Bd + r * GPITCH + kq, Bb + (size_t)r * K + k0 + kq);
        }
    };

    float acc[2][8][4];
#pragma unroll
    for (int mt = 0; mt < 2; mt++)
#pragma unroll
        for (int nt = 0; nt < 8; nt++)
#pragma unroll
            for (int i = 0; i < 4; i++) acc[mt][nt][i] = 0.f;

    const int nk = K / 32;
    load_stage(0, 0); CP_COMMIT();
    load_stage(1, 1); CP_COMMIT();

    int st = 0;
    for (int kt = 0; kt < nk; kt++) {
        if (kt < nk - 1) { CP_WAIT1(); } else { CP_WAIT0(); }
        __syncthreads();

        if (kt + 2 < nk) {
            int s2 = st + 2; if (s2 >= 3) s2 -= 3;
            load_stage(kt + 2, s2);
            CP_COMMIT();
        }

        const uint32_t asb_u = smf_u + (uint32_t)(st * GST) * 4u;
        const uint32_t bsb_u = asb_u + (uint32_t)OP_ST * 4u;
#pragma unroll
        for (int ks = 0; ks < 4; ks++) {
            const int k0 = ks * 8;
            uint32_t a[2][4];
#pragma unroll
            for (int mt = 0; mt < 2; mt++) {
                const int mr = wm * 32 + mt * 16;
                const int arow = (lane & 7) + (((lane >> 3) & 1) << 3);
                const int acol = (lane >> 4) << 2;
                ldsm_x4(a[mt], asb_u +
                        (uint32_t)((mr + arow) * GPITCH + k0 + acol) * 4u);
            }
            uint32_t b[8][2];
#pragma unroll
            for (int ntp = 0; ntp < 8; ntp += 2) {
                const int nr = wn * 64 + ntp * 8;
                uint32_t bb4[4];
                ldsm_x4(bb4, bsb_u +
                        (uint32_t)((nr + lrow) * GPITCH + k0 + lcol) * 4u);
                b[ntp][0] = bb4[0];     b[ntp][1] = bb4[1];
                b[ntp + 1][0] = bb4[2]; b[ntp + 1][1] = bb4[3];
            }
#pragma unroll
            for (int mt = 0; mt < 2; mt++)
#pragma unroll
                for (int nt = 0; nt < 8; nt++)
                    mma_tf32(acc[mt][nt], a[mt], b[nt]);
        }
        st++; if (st == 3) st = 0;
    }

    const int cm = blockIdx.y * 128 + wm * 32;
    const int cn = blockIdx.x * 128 + wn * 64;
#pragma unroll
    for (int mt = 0; mt < 2; mt++) {
#pragma unroll
        for (int nt = 0; nt < 8; nt++) {
            float* p0 = C + (size_t)(cm + mt * 16 + gid) * N + cn + nt * 8 + 2 * tig;
            float* p1 = p0 + (size_t)8 * N;
            *(float2*)p0 = make_float2(acc[mt][nt][0], acc[mt][nt][1]);
            *(float2*)p1 = make_float2(acc[mt][nt][2], acc[mt][nt][3]);
        }
    }
}

// ---------------------------------------------------------------------------
// Tensor-core flash attention (tf32), causal, GQA. LPT schedule.
// P staged in dead K buffer (3 CTAs/SM). K-frags and P-frags via ldmatrix.
// ---------------------------------------------------------------------------
#define KPITCH 68
#define VPITCH 72
#define PPITCH 68
#define KBUF (64 * KPITCH)
#define VBUF (64 * VPITCH)
#define SMEM_ATTN ((2 * KBUF + 2 * VBUF) * 4)   // 71680 bytes

__global__ __launch_bounds__(128) void attn_tc(
    const float* __restrict__ Q, const float* __restrict__ Kg,
    const float* __restrict__ Vg, float* __restrict__ O)
{
    extern __shared__ char smem_raw[];
    float* sK = (float*)smem_raw;
    float* sV = (float*)(smem_raw + 2 * KBUF * 4);
    const uint32_t sk_u = (uint32_t)__cvta_generic_to_shared(smem_raw);

    const int qt = NQT - 1 - blockIdx.x;   // LPT: big tiles first
    const int h = blockIdx.y, b = blockIdx.z;
    const int kvh = h >> 2;
    const int tid = threadIdx.x;
    const int w = tid >> 5;
    const int lane = tid & 31;
    const int gid = lane >> 2, tig = lane & 3;

    const int qk_row = lane & 7;
    const int qk_col = (lane >> 3) << 2;
    const int p_row  = (lane & 7) + (((lane >> 3) & 1) << 3);
    const int p_col  = (lane >> 4) << 2;

    const int qr0 = qt * 64 + w * 16 + gid;
    const int qr1 = qr0 + 8;

    uint32_t aq[8][4];
    {
        const float* q0 = Q + ((size_t)(b * NSEQ) + qr0) * DMODEL + h * HD;
        const float* q1 = Q + ((size_t)(b * NSEQ) + qr1) * DMODEL + h * HD;
#pragma unroll
        for (int ks = 0; ks < 8; ks++) {
            int d = ks * 8 + tig;
            aq[ks][0] = __float_as_uint(q0[d] * 0.125f);
            aq[ks][1] = __float_as_uint(q1[d] * 0.125f);
            aq[ks][2] = __float_as_uint(q0[d + 4] * 0.125f);
            aq[ks][3] = __float_as_uint(q1[d + 4] * 0.125f);
        }
    }

    float o[8][4];
#pragma unroll
    for (int nt = 0; nt < 8; nt++)
#pragma unroll
        for (int i = 0; i < 4; i++) o[nt][i] = 0.f;
    float m0 = -1e30f, l0 = 0.f, m1 = -1e30f, l1 = 0.f;

    const size_t kvs = NKVH * HD;

    auto load_tile = [&](int t, int st) {
        const float* kb = Kg + (size_t)(b * NSEQ + t * 64) * kvs + kvh * HD;
        const float* vb = Vg + (size_t)(b * NSEQ + t * 64) * kvs + kvh * HD;
        float* dK = sK + st * KBUF;
        float* dV = sV + st * VBUF;
#pragma unroll
        for (int i = 0; i < 8; i++) {
            int c = tid + i * 128;
            int r = c >> 4, c4 = (c & 15) << 2;
            cp_async16(dK + r * KPITCH + c4, kb + (size_t)r * kvs + c4);
            cp_async16(dV + r * VPITCH + c4, vb + (size_t)r * kvs + c4);
        }
    };

    load_tile(0, 0);
    CP_COMMIT();

    for (int t = 0; t <= qt; t++) {
        const int st = t & 1;
        CP_WAIT0();
        __syncthreads();

        if (t < qt) { load_tile(t + 1, st ^ 1); CP_COMMIT(); }

        const uint32_t bk_u = sk_u + (uint32_t)(st * KBUF) * 4u;
        const float* bV = sV + st * VBUF;

        float s[8][4];
#pragma unroll
        for (int nt = 0; nt < 8; nt++)
#pragma unroll
            for (int i = 0; i < 4; i++) s[nt][i] = 0.f;
#pragma unroll
        for (int ksp = 0; ksp < 4; ksp++) {
            const int d0 = ksp * 16;
#pragma unroll
            for (int nt = 0; nt < 8; nt++) {
                uint32_t bb4[4];
                ldsm_x4(bb4, bk_u +
                    (uint32_t)(((nt * 8 + qk_row) * KPITCH) + d0 + qk_col) * 4u);
                mma_tf32(s[nt], aq[2 * ksp],     bb4 + 0);
                mma_tf32(s[nt], aq[2 * ksp + 1], bb4 + 2);
            }
        }

        if (t == qt) {
#pragma unroll
            for (int nt = 0; nt < 8; nt++) {
                int k0 = nt * 8 + 2 * tig;
                int r0 = w * 16 + gid;
                if (k0 > r0)         s[nt][0] = -1e30f;
                if (k0 + 1 > r0)     s[nt][1] = -1e30f;
                if (k0 > r0 + 8)     s[nt][2] = -1e30f;
                if (k0 + 1 > r0 + 8) s[nt][3] = -1e30f;
            }
        }

        float mx0 = -1e30f, mx1 = -1e30f;
#pragma unroll
        for (int nt = 0; nt < 8; nt++) {
            mx0 = fmaxf(mx0, fmaxf(s[nt][0], s[nt][1]));
            mx1 = fmaxf(mx1, fmaxf(s[nt][2], s[nt][3]));
        }
        mx0 = fmaxf(mx0, __shfl_xor_sync(0xffffffffu, mx0, 1));
        mx0 = fmaxf(mx0, __shfl_xor_sync(0xffffffffu, mx0, 2));
        mx1 = fmaxf(mx1, __shfl_xor_sync(0xffffffffu, mx1, 1));
        mx1 = fmaxf(mx1, __shfl_xor_sync(0xffffffffu, mx1, 2));

        float mn0 = fmaxf(m0, mx0), mn1 = fmaxf(m1, mx1);
        float c0 = __expf(m0 - mn0), c1 = __expf(m1 - mn1);
        float ls0 = 0.f, ls1 = 0.f;
#pragma unroll
        for (int nt = 0; nt < 8; nt++) {
            s[nt][0] = __expf(s[nt][0] - mn0);
            s[nt][1] = __expf(s[nt][1] - mn0);
            s[nt][2] = __expf(s[nt][2] - mn1);
            s[nt][3] = __expf(s[nt][3] - mn1);
            ls0 += s[nt][0] + s[nt][1];
            ls1 += s[nt][2] + s[nt][3];
        }
        ls0 += __shfl_xor_sync(0xffffffffu, ls0, 1);
        ls0 += __shfl_xor_sync(0xffffffffu, ls0, 2);
        ls1 += __shfl_xor_sync(0xffffffffu, ls1, 1);
        ls1 += __shfl_xor_sync(0xffffffffu, ls1, 2);
        l0 = l0 * c0 + ls0;
        l1 = l1 * c1 + ls1;
        m0 = mn0; m1 = mn1;
#pragma unroll
        for (int nt = 0; nt < 8; nt++) {
            o[nt][0] *= c0; o[nt][1] *= c0;
            o[nt][2] *= c1; o[nt][3] *= c1;
        }

        __syncthreads();   // finish K reads before P overwrites stage st

        uint32_t* pw = (uint32_t*)(sK + st * KBUF) + w * (16 * PPITCH);
        const uint32_t pw_u = sk_u +
            (uint32_t)(st * KBUF + w * (16 * PPITCH)) * 4u;
#pragma unroll
        for (int nt = 0; nt < 8; nt++) {
            uint2 v0 = make_uint2(f2tf32(s[nt][0]), f2tf32(s[nt][1]));
            uint2 v1 = make_uint2(f2tf32(s[nt][2]), f2tf32(s[nt][3]));
            *(uint2*)(pw + gid * PPITCH + nt * 8 + 2 * tig) = v0;
            *(uint2*)(pw + (gid + 8) * PPITCH + nt * 8 + 2 * tig) = v1;
        }
        __syncwarp();

#pragma unroll
        for (int ks = 0; ks < 8; ks++) {
            const int k0 = ks * 8;
            uint32_t ap[4];
            ldsm_x4(ap, pw_u + (uint32_t)(p_row * PPITCH + k0 + p_col) * 4u);
#pragma unroll
            for (int nt = 0; nt < 8; nt++) {
                const float* vr = bV + (k0 + tig) * VPITCH + nt * 8 + gid;
                uint32_t bb[2];
                bb[0] = __float_as_uint(vr[0]);
                bb[1] = __float_as_uint(vr[4 * VPITCH]);
                mma_tf32(o[nt], ap, bb);
            }
        }
    }

    float inv0 = 1.f / l0, inv1 = 1.f / l1;
    float* o0 = O + ((size_t)(b * NSEQ) + qr0) * DMODEL + h * HD;
    float* o1 = O + ((size_t)(b * NSEQ) + qr1) * DMODEL + h * HD;
#pragma unroll
    for (int nt = 0; nt < 8; nt++) {
        *(float2*)(o0 + nt * 8 + 2 * tig) =
            make_float2(roundtf(o[nt][0] * inv0), roundtf(o[nt][1] * inv0));
        *(float2*)(o1 + nt * 8 + 2 * tig) =
            make_float2(roundtf(o[nt][2] * inv1), roundtf(o[nt][3] * inv1));
    }
}

// ---------------------------------------------------------------------------
// Launch. Order: round_x(1), tr_all(2), qkv(3), attn(4 = ncu slot), O-gemm(5).
// ---------------------------------------------------------------------------
extern "C" void kernel_launch(void* const* d_in, const int* in_sizes, int n_in,
                              void* d_out, int out_size)
{
    const float* x  = (const float*)d_in[0];
    const float* Wq = (const float*)d_in[1];
    const float* Wk = (const float*)d_in[2];
    const float* Wv = (const float*)d_in[3];
    const float* Wo = (const float*)d_in[4];
    const float* fc = (const float*)d_in[5];
    const float* fs = (const float*)d_in[6];
    float* out = (float*)d_out;

    float *Qp, *Kp, *Vp, *Op, *xr, *Wqt, *Wkt, *Wvt, *Wot;
    cudaGetSymbolAddress((void**)&Qp,  g_Q);
    cudaGetSymbolAddress((void**)&Kp,  g_K);
    cudaGetSymbolAddress((void**)&Vp,  g_V);
    cudaGetSymbolAddress((void**)&Op,  g_O);
    cudaGetSymbolAddress((void**)&xr,  g_xr);
    cudaGetSymbolAddress((void**)&Wqt, g_Wqt);
    cudaGetSymbolAddress((void**)&Wkt, g_Wkt);
    cudaGetSymbolAddress((void**)&Wvt, g_Wvt);
    cudaGetSymbolAddress((void**)&Wot, g_Wot);

    static bool attr_set = false;
    if (!attr_set) {
        cudaFuncSetAttribute(attn_tc,
            cudaFuncAttributeMaxDynamicSharedMemorySize, SMEM_ATTN);
        cudaFuncSetAttribute(qkv_gemm,
            cudaFuncAttributeMaxDynamicSharedMemorySize, GEMM_DYN);
        cudaFuncSetAttribute(tf32gemm,
            cudaFuncAttributeMaxDynamicSharedMemorySize, GEMM_DYN);
        attr_set = true;
    }

    // 1: round x to tf32
    round_x<<<(N4_X + 1023) / 1024, 1024>>>((const float4*)x, (float4*)xr);

    // 2: transpose+round all weights -> [N,K]
    tr_all<<<dim3(4096, 4), 256>>>(Wq, Wk, Wv, Wo, Wqt, Wkt, Wvt, Wot);

    // 3: fused Q/K/V projection + RoPE (B via transposed weights + ldmatrix)
    qkv_gemm<<<dim3(24, ROWS / 128), 256, GEMM_DYN>>>(
        xr, Wqt, Wkt, Wvt, Qp, Kp, Vp, fc, fs);

    // 4: attention  <-- ncu capture slot
    attn_tc<<<dim3(NQT, NH, BATCH), 128, SMEM_ATTN>>>(Qp, Kp, Vp, Op);

    // 5: output projection
    tf32gemm<<<dim3(DMODEL / 128, ROWS / 128), 256, GEMM_DYN>>>(
        Op, Wot, out, ROWS, DMODEL, DMODEL);
}